// round 2
// baseline (speedup 1.0000x reference)
#include <cuda_runtime.h>
#include <cstdint>

#define BB 16
#define NN 2048
#define DG 512
#define DH 512
#define OUTD 512
#define KTOP 512

typedef unsigned long long u64;
union F2u { u64 u; float2 f; };

// scratch (no cudaMalloc allowed)
__device__ float g_e1[BB * NN * OUTD];
__device__ float g_e2[BB * NN * OUTD];
__device__ float g_hb1[BB * OUTD];
__device__ float g_hb2[BB * OUTD];
__device__ unsigned int g_minbits[BB];
__device__ float g_dinv[BB * NN];

__device__ __forceinline__ unsigned int fmap(float f) {
    unsigned int u = __float_as_uint(f);
    return (u & 0x80000000u) ? ~u : (u | 0x80000000u);
}
__device__ __forceinline__ float funmap(unsigned int m) {
    unsigned int u = (m & 0x80000000u) ? (m ^ 0x80000000u) : ~m;
    return __uint_as_float(u);
}

// packed fp32x2 helpers (Blackwell double-rate fp32; exact IEEE fp32 per lane)
__device__ __forceinline__ u64 dup_f32(float x) {
    u64 r;
    asm("mov.b64 %0, {%1, %1};" : "=l"(r) : "f"(x));
    return r;
}
__device__ __forceinline__ void fma_x2(u64& d, u64 a, u64 b) {
    asm("fma.rn.f32x2 %0, %1, %2, %0;" : "+l"(d) : "l"(a), "l"(b));
}

__global__ void k_init() {
    if (threadIdx.x < BB) g_minbits[threadIdx.x] = 0xFFFFFFFFu;
}

// per-batch hidden contribution: g_hb[b,o] = sum_d h[b,d] * W[512+d, o]
__global__ void k_hb(const float* __restrict__ hidden,
                     const float* __restrict__ W1,
                     const float* __restrict__ W2) {
    int b = blockIdx.x;
    int o = threadIdx.x;  // 512 threads
    const float* h = hidden + b * DH;
    float a1 = 0.f, a2 = 0.f;
#pragma unroll 4
    for (int d = 0; d < DH; d++) {
        float hv = h[d];
        a1 = fmaf(hv, W1[(size_t)(DG + d) * OUTD + o], a1);
        a2 = fmaf(hv, W2[(size_t)(DG + d) * OUTD + o], a2);
    }
    g_hb1[b * OUTD + o] = a1;
    g_hb2[b * OUTD + o] = a2;
}

#define BM 128
#define BN 128
#define BK 16

// e1/e2 GEMM: C[32768, 1024] = ge[32768,512] @ W[512,1024] (+ hb, bias, mask)
// Each block covers 128 output cols entirely inside W1 (bn<4) or W2 (bn>=4).
__global__ __launch_bounds__(256) void k_gemm1(
    const float* __restrict__ ge, const float* __restrict__ mask,
    const float* __restrict__ W1, const float* __restrict__ b1,
    const float* __restrict__ W2, const float* __restrict__ b2) {
    __shared__ float As[BK][BM];
    __shared__ float Bs[BK][BN];
    int bn = blockIdx.x, bm = blockIdx.y;
    int tid = threadIdx.x;
    int tx = tid % 16, ty = tid / 16;
    int row0 = bm * BM;
    int col0 = bn * BN;

    const float* W;
    const float* bias;
    const float* hb;
    float* dst;
    if (col0 < OUTD) {
        W = W1; bias = b1; hb = g_hb1; dst = g_e1;
    } else {
        W = W2; bias = b2; hb = g_hb2; dst = g_e2;
        col0 -= OUTD;
    }

    int a_row = tid / 4;
    int a_k4 = (tid % 4) * 4;
    int b_k = tid / 32;
    int b_n4 = (tid % 32) * 4;

    u64 acc[8][4];
#pragma unroll
    for (int i = 0; i < 8; i++)
#pragma unroll
        for (int j = 0; j < 4; j++) acc[i][j] = 0ull;

    for (int k0 = 0; k0 < DG; k0 += BK) {
#pragma unroll
        for (int r = 0; r < 2; r++) {
            int row = a_row + r * 64;
            float4 v = *(const float4*)(ge + (size_t)(row0 + row) * DG + k0 + a_k4);
            As[a_k4 + 0][row] = v.x;
            As[a_k4 + 1][row] = v.y;
            As[a_k4 + 2][row] = v.z;
            As[a_k4 + 3][row] = v.w;
        }
#pragma unroll
        for (int r = 0; r < 2; r++) {
            int kk = b_k + r * 8;
            *(float4*)&Bs[kk][b_n4] =
                *(const float4*)(W + (size_t)(k0 + kk) * OUTD + col0 + b_n4);
        }
        __syncthreads();
#pragma unroll
        for (int kk = 0; kk < BK; kk++) {
            float4 a0 = *(const float4*)&As[kk][ty * 8];
            float4 a1v = *(const float4*)&As[kk][ty * 8 + 4];
            ulonglong2 bq0 = *(const ulonglong2*)&Bs[kk][tx * 8];
            ulonglong2 bq1 = *(const ulonglong2*)&Bs[kk][tx * 8 + 4];
            u64 bp[4] = {bq0.x, bq0.y, bq1.x, bq1.y};
            float av[8] = {a0.x, a0.y, a0.z, a0.w, a1v.x, a1v.y, a1v.z, a1v.w};
#pragma unroll
            for (int i = 0; i < 8; i++) {
                u64 ad = dup_f32(av[i]);
#pragma unroll
                for (int j = 0; j < 4; j++) fma_x2(acc[i][j], ad, bp[j]);
            }
        }
        __syncthreads();
    }

#pragma unroll
    for (int i = 0; i < 8; i++) {
        int m = row0 + ty * 8 + i;
        int b = m >> 11;
        float mk = mask[m];
#pragma unroll
        for (int j = 0; j < 4; j++) {
            F2u c;
            c.u = acc[i][j];
            int n = col0 + tx * 8 + j * 2;
            dst[(size_t)m * OUTD + n] = mk * (c.f.x + hb[b * OUTD + n]) + bias[n];
            dst[(size_t)m * OUTD + n + 1] = mk * (c.f.y + hb[b * OUTD + n + 1]) + bias[n + 1];
        }
    }
}

// batched Adj = e1 @ e2^T, raw values to out; fused per-batch min (atomicMin on mapped bits)
__global__ __launch_bounds__(256) void k_gemm2(float* __restrict__ out) {
    __shared__ float As[BK][BM];
    __shared__ float Bs[BK][BN];
    __shared__ unsigned int sMin;
    int b = blockIdx.z;
    int bn = blockIdx.x, bm = blockIdx.y;
    int tid = threadIdx.x;
    int tx = tid % 16, ty = tid / 16;
    int row0 = bm * BM, col0 = bn * BN;
    const float* e1p = g_e1 + (size_t)b * NN * OUTD;
    const float* e2p = g_e2 + (size_t)b * NN * OUTD;

    int a_row = tid / 4;
    int a_k4 = (tid % 4) * 4;

    if (tid == 0) sMin = 0xFFFFFFFFu;

    u64 acc[8][4];
#pragma unroll
    for (int i = 0; i < 8; i++)
#pragma unroll
        for (int j = 0; j < 4; j++) acc[i][j] = 0ull;

    for (int k0 = 0; k0 < OUTD; k0 += BK) {
#pragma unroll
        for (int r = 0; r < 2; r++) {
            int row = a_row + r * 64;
            float4 v = *(const float4*)(e1p + (size_t)(row0 + row) * OUTD + k0 + a_k4);
            As[a_k4 + 0][row] = v.x;
            As[a_k4 + 1][row] = v.y;
            As[a_k4 + 2][row] = v.z;
            As[a_k4 + 3][row] = v.w;
            float4 w = *(const float4*)(e2p + (size_t)(col0 + row) * OUTD + k0 + a_k4);
            Bs[a_k4 + 0][row] = w.x;
            Bs[a_k4 + 1][row] = w.y;
            Bs[a_k4 + 2][row] = w.z;
            Bs[a_k4 + 3][row] = w.w;
        }
        __syncthreads();
#pragma unroll
        for (int kk = 0; kk < BK; kk++) {
            float4 a0 = *(const float4*)&As[kk][ty * 8];
            float4 a1v = *(const float4*)&As[kk][ty * 8 + 4];
            ulonglong2 bq0 = *(const ulonglong2*)&Bs[kk][tx * 8];
            ulonglong2 bq1 = *(const ulonglong2*)&Bs[kk][tx * 8 + 4];
            u64 bp[4] = {bq0.x, bq0.y, bq1.x, bq1.y};
            float av[8] = {a0.x, a0.y, a0.z, a0.w, a1v.x, a1v.y, a1v.z, a1v.w};
#pragma unroll
            for (int i = 0; i < 8; i++) {
                u64 ad = dup_f32(av[i]);
#pragma unroll
                for (int j = 0; j < 4; j++) fma_x2(acc[i][j], ad, bp[j]);
            }
        }
        __syncthreads();
    }

    float lmin = 3.402823466e+38f;
    float* outb = out + (size_t)b * NN * NN;
#pragma unroll
    for (int i = 0; i < 8; i++) {
        int m = row0 + ty * 8 + i;
        float* op = outb + (size_t)m * NN + col0 + tx * 8;
        F2u c0, c1, c2, c3;
        c0.u = acc[i][0];
        c1.u = acc[i][1];
        c2.u = acc[i][2];
        c3.u = acc[i][3];
        float4 v0 = make_float4(c0.f.x, c0.f.y, c1.f.x, c1.f.y);
        float4 v1 = make_float4(c2.f.x, c2.f.y, c3.f.x, c3.f.y);
        *(float4*)op = v0;
        *(float4*)(op + 4) = v1;
        lmin = fminf(lmin, fminf(fminf(fminf(v0.x, v0.y), fminf(v0.z, v0.w)),
                                 fminf(fminf(v1.x, v1.y), fminf(v1.z, v1.w))));
    }
#pragma unroll
    for (int off = 16; off > 0; off >>= 1)
        lmin = fminf(lmin, __shfl_xor_sync(0xFFFFFFFFu, lmin, off));
    if ((tid & 31) == 0) atomicMin(&sMin, fmap(lmin));
    __syncthreads();
    if (tid == 0) atomicMin(&g_minbits[b], sMin);
}

// per-row: min-shift, mask, exact top-k(512) with jax tie semantics, rowsum, scale by d_i
#define RT 256
#define EPT (NN / RT)  // 8
__global__ __launch_bounds__(RT) void k_row(float* __restrict__ out,
                                            const float* __restrict__ mask) {
    __shared__ float vals[NN];
    __shared__ unsigned int keys[NN];
    __shared__ unsigned int hist[256];
    __shared__ unsigned int scan[RT];
    __shared__ unsigned int s_digit, s_r;
    __shared__ float s_sum[RT / 32];
    __shared__ float s_dinv;

    int row = blockIdx.x;  // global row 0..B*N-1
    int b = row >> 11;
    int tid = threadIdx.x;
    int lane = tid & 31;
    int warp = tid >> 5;
    float minb = funmap(g_minbits[b]);
    float mk = mask[row];
    float* rp = out + (size_t)row * NN;

#pragma unroll
    for (int q = 0; q < EPT; q++) {
        int j = tid + q * RT;
        float v = (rp[j] - minb) * mk;
        vals[j] = v;
        keys[j] = fmap(v);
    }
    __syncthreads();

    // radix select the KTOP-th largest key
    unsigned int prefix = 0;
    unsigned int r = KTOP;
    for (int shift = 24; shift >= 0; shift -= 8) {
        hist[tid] = 0;
        __syncthreads();
        unsigned int pmask = (shift == 24) ? 0u : (0xFFFFFFFFu << (shift + 8));
        int base = tid * EPT;
#pragma unroll
        for (int q = 0; q < EPT; q++) {
            unsigned int k = keys[base + q];
            bool match = ((k & pmask) == prefix);
            unsigned int d = match ? ((k >> shift) & 0xFFu) : 0xFFFFFFFFu;
            unsigned int peers = __match_any_sync(0xFFFFFFFFu, d);
            if (match && (lane == (__ffs(peers) - 1)))
                atomicAdd(&hist[d], __popc(peers));
        }
        __syncthreads();
        // parallel suffix-sum of hist -> scan
        scan[tid] = hist[tid];
        __syncthreads();
#pragma unroll
        for (int off = 1; off < 256; off <<= 1) {
            unsigned int t = (tid + off < 256) ? scan[tid + off] : 0u;
            __syncthreads();
            scan[tid] += t;
            __syncthreads();
        }
        unsigned int snext = (tid == 255) ? 0u : scan[tid + 1];
        if (scan[tid] >= r && snext < r) {
            s_digit = (unsigned int)tid;
            s_r = r - snext;
        }
        __syncthreads();
        prefix |= (s_digit << shift);
        r = s_r;
        __syncthreads();
    }
    unsigned int T = prefix;
    unsigned int eq_needed = r;

    // stable (lowest-index-first) resolution among keys == T
    int base = tid * EPT;
    unsigned int cnt = 0;
#pragma unroll
    for (int q = 0; q < EPT; q++) cnt += (keys[base + q] == T) ? 1u : 0u;
    scan[tid] = cnt;
    __syncthreads();
#pragma unroll
    for (int off = 1; off < RT; off <<= 1) {
        unsigned int t = (tid >= off) ? scan[tid - off] : 0u;
        __syncthreads();
        scan[tid] += t;
        __syncthreads();
    }
    unsigned int rank = scan[tid] - cnt;  // exclusive prefix

    float lsum = 0.f;
#pragma unroll
    for (int q = 0; q < EPT; q++) {
        int j = base + q;
        unsigned int k = keys[j];
        bool keep = (k > T) || (k == T && rank < eq_needed);
        if (k == T) rank++;
        float v = keep ? vals[j] : 0.0f;
        vals[j] = v;
        lsum += v;
    }
#pragma unroll
    for (int off = 16; off > 0; off >>= 1) lsum += __shfl_xor_sync(0xFFFFFFFFu, lsum, off);
    if (lane == 0) s_sum[warp] = lsum;
    __syncthreads();
    if (tid == 0) {
        float tot = 0.f;
#pragma unroll
        for (int w = 0; w < RT / 32; w++) tot += s_sum[w];
        float d = (tot > 0.f) ? (1.0f / sqrtf(tot)) : 0.0f;
        g_dinv[row] = d;
        s_dinv = d;
    }
    __syncthreads();
    float dinv = s_dinv;
#pragma unroll
    for (int q = 0; q < EPT; q++) {
        int j = tid + q * RT;
        rp[j] = vals[j] * dinv;  // d_i * A ; d_j applied in k_scale
    }
}

// out[b,i,j] *= d[b,j]
__global__ __launch_bounds__(256) void k_scale(float* __restrict__ out) {
    size_t idx4 = (size_t)blockIdx.x * blockDim.x + threadIdx.x;  // 16777216 float4s
    float4 v = ((float4*)out)[idx4];
    size_t col4 = idx4 & (NN / 4 - 1);
    size_t rowg = idx4 >> 9;
    size_t b = rowg >> 11;
    float4 dj = ((const float4*)g_dinv)[(b << 9) + col4];
    v.x *= dj.x;
    v.y *= dj.y;
    v.z *= dj.z;
    v.w *= dj.w;
    ((float4*)out)[idx4] = v;
}

extern "C" void kernel_launch(void* const* d_in, const int* in_sizes, int n_in,
                              void* d_out, int out_size) {
    const float* ge = (const float*)d_in[0];
    const float* mask = (const float*)d_in[1];
    const float* hs = (const float*)d_in[2];
    const float* W1 = (const float*)d_in[3];
    const float* b1 = (const float*)d_in[4];
    const float* W2 = (const float*)d_in[5];
    const float* b2 = (const float*)d_in[6];
    float* out = (float*)d_out;

    k_init<<<1, 32>>>();
    k_hb<<<BB, 512>>>(hs, W1, W2);
    k_gemm1<<<dim3(1024 / BN, (BB * NN) / BM), 256>>>(ge, mask, W1, b1, W2, b2);
    k_gemm2<<<dim3(NN / BN, NN / BM, BB), 256>>>(out);
    k_row<<<BB * NN, RT>>>(out, mask);
    k_scale<<<65536, 256>>>(out);
}

// round 3
// speedup vs baseline: 1.0776x; 1.0776x over previous
#include <cuda_runtime.h>
#include <cstdint>

#define BB 16
#define NN 2048
#define DG 512
#define DH 512
#define OUTD 512
#define KTOP 512

typedef unsigned long long u64;
union F2u { u64 u; float2 f; };

// scratch (no cudaMalloc allowed)
__device__ float g_e1[BB * NN * OUTD];
__device__ float g_e2[BB * NN * OUTD];
__device__ float g_hb1[BB * OUTD];
__device__ float g_hb2[BB * OUTD];
__device__ unsigned int g_minbits[BB];
__device__ float g_dinv[BB * NN];

__device__ __forceinline__ unsigned int fmap(float f) {
    unsigned int u = __float_as_uint(f);
    return (u & 0x80000000u) ? ~u : (u | 0x80000000u);
}
__device__ __forceinline__ float funmap(unsigned int m) {
    unsigned int u = (m & 0x80000000u) ? (m ^ 0x80000000u) : ~m;
    return __uint_as_float(u);
}

// packed fp32x2 helpers (Blackwell double-rate fp32; exact IEEE fp32 per lane)
__device__ __forceinline__ u64 dup_f32(float x) {
    u64 r;
    asm("mov.b64 %0, {%1, %1};" : "=l"(r) : "f"(x));
    return r;
}
__device__ __forceinline__ void fma_x2(u64& d, u64 a, u64 b) {
    asm("fma.rn.f32x2 %0, %1, %2, %0;" : "+l"(d) : "l"(a), "l"(b));
}

__global__ void k_init() {
    if (threadIdx.x < BB) g_minbits[threadIdx.x] = 0xFFFFFFFFu;
}

// per-batch hidden contribution: g_hb[b,o] = sum_d h[b,d] * W[512+d, o]
__global__ void k_hb(const float* __restrict__ hidden,
                     const float* __restrict__ W1,
                     const float* __restrict__ W2) {
    int b = blockIdx.x;
    int o = threadIdx.x;  // 512 threads
    const float* h = hidden + b * DH;
    float a1 = 0.f, a2 = 0.f;
#pragma unroll 4
    for (int d = 0; d < DH; d++) {
        float hv = h[d];
        a1 = fmaf(hv, W1[(size_t)(DG + d) * OUTD + o], a1);
        a2 = fmaf(hv, W2[(size_t)(DG + d) * OUTD + o], a2);
    }
    g_hb1[b * OUTD + o] = a1;
    g_hb2[b * OUTD + o] = a2;
}

#define BM 128
#define BN 128
#define BK 16

// e1/e2 GEMM: C[32768, 1024] = ge[32768,512] @ W[512,1024] (+ hb, bias, mask)
// acc packed over M (pairs of consecutive rows); A pairs load directly from smem.
__global__ __launch_bounds__(256, 2) void k_gemm1(
    const float* __restrict__ ge, const float* __restrict__ mask,
    const float* __restrict__ W1, const float* __restrict__ b1,
    const float* __restrict__ W2, const float* __restrict__ b2) {
    __shared__ float As[BK][BM];
    __shared__ float Bs[BK][BN];
    int bn = blockIdx.x, bm = blockIdx.y;
    int tid = threadIdx.x;
    int tx = tid % 16, ty = tid / 16;
    int row0 = bm * BM;
    int col0 = bn * BN;

    const float* W;
    const float* bias;
    const float* hb;
    float* dst;
    if (col0 < OUTD) {
        W = W1; bias = b1; hb = g_hb1; dst = g_e1;
    } else {
        W = W2; bias = b2; hb = g_hb2; dst = g_e2;
        col0 -= OUTD;
    }

    int a_row = tid / 4;
    int a_k4 = (tid % 4) * 4;
    int b_k = tid / 32;
    int b_n4 = (tid % 32) * 4;

    u64 acc[4][8];  // [row-pair][col]
#pragma unroll
    for (int i = 0; i < 4; i++)
#pragma unroll
        for (int j = 0; j < 8; j++) acc[i][j] = 0ull;

    for (int k0 = 0; k0 < DG; k0 += BK) {
#pragma unroll
        for (int r = 0; r < 2; r++) {
            int row = a_row + r * 64;
            float4 v = *(const float4*)(ge + (size_t)(row0 + row) * DG + k0 + a_k4);
            As[a_k4 + 0][row] = v.x;
            As[a_k4 + 1][row] = v.y;
            As[a_k4 + 2][row] = v.z;
            As[a_k4 + 3][row] = v.w;
        }
#pragma unroll
        for (int r = 0; r < 2; r++) {
            int kk = b_k + r * 8;
            *(float4*)&Bs[kk][b_n4] =
                *(const float4*)(W + (size_t)(k0 + kk) * OUTD + col0 + b_n4);
        }
        __syncthreads();
#pragma unroll
        for (int kk = 0; kk < BK; kk++) {
            ulonglong2 aq0 = *(const ulonglong2*)&As[kk][ty * 8];
            ulonglong2 aq1 = *(const ulonglong2*)&As[kk][ty * 8 + 4];
            u64 ap[4] = {aq0.x, aq0.y, aq1.x, aq1.y};
            float4 bv0 = *(const float4*)&Bs[kk][tx * 8];
            float4 bv1 = *(const float4*)&Bs[kk][tx * 8 + 4];
            float bv[8] = {bv0.x, bv0.y, bv0.z, bv0.w, bv1.x, bv1.y, bv1.z, bv1.w};
#pragma unroll
            for (int j = 0; j < 8; j++) {
                u64 bd = dup_f32(bv[j]);
#pragma unroll
                for (int i = 0; i < 4; i++) fma_x2(acc[i][j], ap[i], bd);
            }
        }
        __syncthreads();
    }

#pragma unroll
    for (int i = 0; i < 4; i++) {
        int m0 = row0 + ty * 8 + i * 2;
        int b = m0 >> 11;
        float mk0 = mask[m0];
        float mk1 = mask[m0 + 1];
#pragma unroll
        for (int j = 0; j < 8; j++) {
            F2u c;
            c.u = acc[i][j];
            int n = col0 + tx * 8 + j;
            float hbn = hb[b * OUTD + n];
            float bn_ = bias[n];
            dst[(size_t)m0 * OUTD + n] = mk0 * (c.f.x + hbn) + bn_;
            dst[(size_t)(m0 + 1) * OUTD + n] = mk1 * (c.f.y + hbn) + bn_;
        }
    }
}

// batched Adj = e1 @ e2^T, raw values to out; fused per-batch min (atomicMin on mapped bits)
__global__ __launch_bounds__(256, 2) void k_gemm2(float* __restrict__ out) {
    __shared__ float As[BK][BM];
    __shared__ float Bs[BK][BN];
    __shared__ unsigned int sMin;
    int b = blockIdx.z;
    int bn = blockIdx.x, bm = blockIdx.y;
    int tid = threadIdx.x;
    int tx = tid % 16, ty = tid / 16;
    int row0 = bm * BM, col0 = bn * BN;
    const float* e1p = g_e1 + (size_t)b * NN * OUTD;
    const float* e2p = g_e2 + (size_t)b * NN * OUTD;

    int a_row = tid / 4;
    int a_k4 = (tid % 4) * 4;

    if (tid == 0) sMin = 0xFFFFFFFFu;

    u64 acc[4][8];  // [row-pair][col]
#pragma unroll
    for (int i = 0; i < 4; i++)
#pragma unroll
        for (int j = 0; j < 8; j++) acc[i][j] = 0ull;

    for (int k0 = 0; k0 < OUTD; k0 += BK) {
#pragma unroll
        for (int r = 0; r < 2; r++) {
            int row = a_row + r * 64;
            float4 v = *(const float4*)(e1p + (size_t)(row0 + row) * OUTD + k0 + a_k4);
            As[a_k4 + 0][row] = v.x;
            As[a_k4 + 1][row] = v.y;
            As[a_k4 + 2][row] = v.z;
            As[a_k4 + 3][row] = v.w;
            float4 w = *(const float4*)(e2p + (size_t)(col0 + row) * OUTD + k0 + a_k4);
            Bs[a_k4 + 0][row] = w.x;
            Bs[a_k4 + 1][row] = w.y;
            Bs[a_k4 + 2][row] = w.z;
            Bs[a_k4 + 3][row] = w.w;
        }
        __syncthreads();
#pragma unroll
        for (int kk = 0; kk < BK; kk++) {
            ulonglong2 aq0 = *(const ulonglong2*)&As[kk][ty * 8];
            ulonglong2 aq1 = *(const ulonglong2*)&As[kk][ty * 8 + 4];
            u64 ap[4] = {aq0.x, aq0.y, aq1.x, aq1.y};
            float4 bv0 = *(const float4*)&Bs[kk][tx * 8];
            float4 bv1 = *(const float4*)&Bs[kk][tx * 8 + 4];
            float bv[8] = {bv0.x, bv0.y, bv0.z, bv0.w, bv1.x, bv1.y, bv1.z, bv1.w};
#pragma unroll
            for (int j = 0; j < 8; j++) {
                u64 bd = dup_f32(bv[j]);
#pragma unroll
                for (int i = 0; i < 4; i++) fma_x2(acc[i][j], ap[i], bd);
            }
        }
        __syncthreads();
    }

    float lmin = 3.402823466e+38f;
    float* outb = out + (size_t)b * NN * NN;
#pragma unroll
    for (int i = 0; i < 4; i++) {
        int m0 = row0 + ty * 8 + i * 2;
        float* op0 = outb + (size_t)m0 * NN + col0 + tx * 8;
        float* op1 = op0 + NN;
        F2u c0, c1, c2, c3, c4, c5, c6, c7;
        c0.u = acc[i][0]; c1.u = acc[i][1]; c2.u = acc[i][2]; c3.u = acc[i][3];
        c4.u = acc[i][4]; c5.u = acc[i][5]; c6.u = acc[i][6]; c7.u = acc[i][7];
        float4 r0a = make_float4(c0.f.x, c1.f.x, c2.f.x, c3.f.x);
        float4 r0b = make_float4(c4.f.x, c5.f.x, c6.f.x, c7.f.x);
        float4 r1a = make_float4(c0.f.y, c1.f.y, c2.f.y, c3.f.y);
        float4 r1b = make_float4(c4.f.y, c5.f.y, c6.f.y, c7.f.y);
        *(float4*)op0 = r0a;
        *(float4*)(op0 + 4) = r0b;
        *(float4*)op1 = r1a;
        *(float4*)(op1 + 4) = r1b;
        lmin = fminf(lmin, fminf(fminf(fminf(r0a.x, r0a.y), fminf(r0a.z, r0a.w)),
                                 fminf(fminf(r0b.x, r0b.y), fminf(r0b.z, r0b.w))));
        lmin = fminf(lmin, fminf(fminf(fminf(r1a.x, r1a.y), fminf(r1a.z, r1a.w)),
                                 fminf(fminf(r1b.x, r1b.y), fminf(r1b.z, r1b.w))));
    }
#pragma unroll
    for (int off = 16; off > 0; off >>= 1)
        lmin = fminf(lmin, __shfl_xor_sync(0xFFFFFFFFu, lmin, off));
    if ((tid & 31) == 0) atomicMin(&sMin, fmap(lmin));
    __syncthreads();
    if (tid == 0) atomicMin(&g_minbits[b], sMin);
}

// per-row: min-shift, mask, exact top-k(512) with jax tie semantics, rowsum, scale by d_i
#define RT 256
#define EPT (NN / RT)  // 8
__global__ __launch_bounds__(RT) void k_row(float* __restrict__ out,
                                            const float* __restrict__ mask) {
    __shared__ float vals[NN];
    __shared__ unsigned int keys[NN];
    __shared__ unsigned int hist[256];
    __shared__ unsigned int scan[RT];
    __shared__ unsigned int s_digit, s_r;
    __shared__ float s_sum[RT / 32];
    __shared__ float s_dinv;

    int row = blockIdx.x;  // global row 0..B*N-1
    int b = row >> 11;
    int tid = threadIdx.x;
    int lane = tid & 31;
    int warp = tid >> 5;
    float minb = funmap(g_minbits[b]);
    float mk = mask[row];
    float* rp = out + (size_t)row * NN;

#pragma unroll
    for (int q = 0; q < EPT; q++) {
        int j = tid + q * RT;
        float v = (rp[j] - minb) * mk;
        vals[j] = v;
        keys[j] = fmap(v);
    }
    __syncthreads();

    // radix select the KTOP-th largest key
    unsigned int prefix = 0;
    unsigned int r = KTOP;
    for (int shift = 24; shift >= 0; shift -= 8) {
        hist[tid] = 0;
        __syncthreads();
        unsigned int pmask = (shift == 24) ? 0u : (0xFFFFFFFFu << (shift + 8));
        int base = tid * EPT;
#pragma unroll
        for (int q = 0; q < EPT; q++) {
            unsigned int k = keys[base + q];
            bool match = ((k & pmask) == prefix);
            unsigned int d = match ? ((k >> shift) & 0xFFu) : 0xFFFFFFFFu;
            unsigned int peers = __match_any_sync(0xFFFFFFFFu, d);
            if (match && (lane == (__ffs(peers) - 1)))
                atomicAdd(&hist[d], __popc(peers));
        }
        __syncthreads();
        // parallel suffix-sum of hist -> scan
        scan[tid] = hist[tid];
        __syncthreads();
#pragma unroll
        for (int off = 1; off < 256; off <<= 1) {
            unsigned int t = (tid + off < 256) ? scan[tid + off] : 0u;
            __syncthreads();
            scan[tid] += t;
            __syncthreads();
        }
        unsigned int snext = (tid == 255) ? 0u : scan[tid + 1];
        if (scan[tid] >= r && snext < r) {
            s_digit = (unsigned int)tid;
            s_r = r - snext;
        }
        __syncthreads();
        prefix |= (s_digit << shift);
        r = s_r;
        __syncthreads();
    }
    unsigned int T = prefix;
    unsigned int eq_needed = r;

    // stable (lowest-index-first) resolution among keys == T
    int base = tid * EPT;
    unsigned int cnt = 0;
#pragma unroll
    for (int q = 0; q < EPT; q++) cnt += (keys[base + q] == T) ? 1u : 0u;
    scan[tid] = cnt;
    __syncthreads();
#pragma unroll
    for (int off = 1; off < RT; off <<= 1) {
        unsigned int t = (tid >= off) ? scan[tid - off] : 0u;
        __syncthreads();
        scan[tid] += t;
        __syncthreads();
    }
    unsigned int rank = scan[tid] - cnt;  // exclusive prefix

    float lsum = 0.f;
#pragma unroll
    for (int q = 0; q < EPT; q++) {
        int j = base + q;
        unsigned int k = keys[j];
        bool keep = (k > T) || (k == T && rank < eq_needed);
        if (k == T) rank++;
        float v = keep ? vals[j] : 0.0f;
        vals[j] = v;
        lsum += v;
    }
#pragma unroll
    for (int off = 16; off > 0; off >>= 1) lsum += __shfl_xor_sync(0xFFFFFFFFu, lsum, off);
    if (lane == 0) s_sum[warp] = lsum;
    __syncthreads();
    if (tid == 0) {
        float tot = 0.f;
#pragma unroll
        for (int w = 0; w < RT / 32; w++) tot += s_sum[w];
        float d = (tot > 0.f) ? (1.0f / sqrtf(tot)) : 0.0f;
        g_dinv[row] = d;
        s_dinv = d;
    }
    __syncthreads();
    float dinv = s_dinv;
#pragma unroll
    for (int q = 0; q < EPT; q++) {
        int j = tid + q * RT;
        rp[j] = vals[j] * dinv;  // d_i * A ; d_j applied in k_scale
    }
}

// out[b,i,j] *= d[b,j]
__global__ __launch_bounds__(256) void k_scale(float* __restrict__ out) {
    size_t idx4 = (size_t)blockIdx.x * blockDim.x + threadIdx.x;  // 16777216 float4s
    float4 v = ((float4*)out)[idx4];
    size_t col4 = idx4 & (NN / 4 - 1);
    size_t rowg = idx4 >> 9;
    size_t b = rowg >> 11;
    float4 dj = ((const float4*)g_dinv)[(b << 9) + col4];
    v.x *= dj.x;
    v.y *= dj.y;
    v.z *= dj.z;
    v.w *= dj.w;
    ((float4*)out)[idx4] = v;
}

extern "C" void kernel_launch(void* const* d_in, const int* in_sizes, int n_in,
                              void* d_out, int out_size) {
    const float* ge = (const float*)d_in[0];
    const float* mask = (const float*)d_in[1];
    const float* hs = (const float*)d_in[2];
    const float* W1 = (const float*)d_in[3];
    const float* b1 = (const float*)d_in[4];
    const float* W2 = (const float*)d_in[5];
    const float* b2 = (const float*)d_in[6];
    float* out = (float*)d_out;

    k_init<<<1, 32>>>();
    k_hb<<<BB, 512>>>(hs, W1, W2);
    k_gemm1<<<dim3(1024 / BN, (BB * NN) / BM), 256>>>(ge, mask, W1, b1, W2, b2);
    k_gemm2<<<dim3(NN / BN, NN / BM, BB), 256>>>(out);
    k_row<<<BB * NN, RT>>>(out, mask);
    k_scale<<<65536, 256>>>(out);
}

// round 4
// speedup vs baseline: 1.1487x; 1.0660x over previous
#include <cuda_runtime.h>
#include <cstdint>

#define BB 16
#define NN 2048
#define DG 512
#define DH 512
#define OUTD 512
#define KTOP 512

// scratch (no cudaMalloc allowed)
__device__ float g_e1[BB * NN * OUTD];
__device__ float g_e2[BB * NN * OUTD];
__device__ float g_hb1[BB * OUTD];
__device__ float g_hb2[BB * OUTD];
__device__ unsigned int g_minbits[BB];
__device__ float g_dinv[BB * NN];
__device__ unsigned int g_T[BB * NN];
__device__ unsigned int g_eq[BB * NN];

__device__ __forceinline__ unsigned int fmap(float f) {
    unsigned int u = __float_as_uint(f);
    return (u & 0x80000000u) ? ~u : (u | 0x80000000u);
}
__device__ __forceinline__ float funmap(unsigned int m) {
    unsigned int u = (m & 0x80000000u) ? (m ^ 0x80000000u) : ~m;
    return __uint_as_float(u);
}

__global__ void k_init() {
    if (threadIdx.x < BB) g_minbits[threadIdx.x] = 0xFFFFFFFFu;
}

// per-batch hidden contribution: g_hb[b,o] = sum_d h[b,d] * W[512+d, o]
__global__ void k_hb(const float* __restrict__ hidden,
                     const float* __restrict__ W1,
                     const float* __restrict__ W2) {
    int b = blockIdx.x;
    int o = threadIdx.x;  // 512 threads
    const float* h = hidden + b * DH;
    float a1 = 0.f, a2 = 0.f;
#pragma unroll 4
    for (int d = 0; d < DH; d++) {
        float hv = h[d];
        a1 = fmaf(hv, W1[(size_t)(DG + d) * OUTD + o], a1);
        a2 = fmaf(hv, W2[(size_t)(DG + d) * OUTD + o], a2);
    }
    g_hb1[b * OUTD + o] = a1;
    g_hb2[b * OUTD + o] = a2;
}

#define BM 128
#define BN 128
#define BK2 8

// e1/e2 GEMM: C[32768, 1024] = ge[32768,512] @ W[512,1024] (+ hb, bias, mask)
// double-buffered smem, BK=8, sequential-K accumulation (bitwise fp32).
__global__ __launch_bounds__(256, 2) void k_gemm1(
    const float* __restrict__ ge, const float* __restrict__ mask,
    const float* __restrict__ W1, const float* __restrict__ b1,
    const float* __restrict__ W2, const float* __restrict__ b2) {
    __shared__ float As[2][BK2][BM];
    __shared__ float Bs[2][BK2][BN];
    int bn = blockIdx.x, bm = blockIdx.y;
    int tid = threadIdx.x;
    int tx = tid % 16, ty = tid / 16;
    int row0 = bm * BM;
    int col0 = bn * BN;

    const float* W;
    const float* bias;
    const float* hb;
    float* dst;
    if (col0 < OUTD) {
        W = W1; bias = b1; hb = g_hb1; dst = g_e1;
    } else {
        W = W2; bias = b2; hb = g_hb2; dst = g_e2;
        col0 -= OUTD;
    }

    int a_row = tid >> 1;           // 0..127
    int a_k4 = (tid & 1) * 4;       // 0 or 4
    int b_k = tid >> 5;             // 0..7
    int b_n4 = (tid & 31) * 4;      // 0..124

    const float* agp = ge + (size_t)(row0 + a_row) * DG + a_k4;
    const float* bgp = W + (size_t)b_k * OUTD + col0 + b_n4;

    float acc[8][8];
#pragma unroll
    for (int i = 0; i < 8; i++)
#pragma unroll
        for (int j = 0; j < 8; j++) acc[i][j] = 0.f;

    // prologue: tile 0
    {
        float4 pa = *(const float4*)agp;
        float4 pb = *(const float4*)bgp;
        As[0][a_k4 + 0][a_row] = pa.x;
        As[0][a_k4 + 1][a_row] = pa.y;
        As[0][a_k4 + 2][a_row] = pa.z;
        As[0][a_k4 + 3][a_row] = pa.w;
        *(float4*)&Bs[0][b_k][b_n4] = pb;
    }
    __syncthreads();

    for (int k0 = 0; k0 < DG; k0 += BK2) {
        int buf = (k0 >> 3) & 1;
        float4 pa, pb;
        bool more = (k0 + BK2) < DG;
        if (more) {
            pa = *(const float4*)(agp + k0 + BK2);
            pb = *(const float4*)(bgp + (size_t)(k0 + BK2) * OUTD);
        }
#pragma unroll
        for (int kk = 0; kk < BK2; kk++) {
            float4 a0 = *(const float4*)&As[buf][kk][ty * 8];
            float4 a1v = *(const float4*)&As[buf][kk][ty * 8 + 4];
            float4 bv0 = *(const float4*)&Bs[buf][kk][tx * 8];
            float4 bv1 = *(const float4*)&Bs[buf][kk][tx * 8 + 4];
            float av[8] = {a0.x, a0.y, a0.z, a0.w, a1v.x, a1v.y, a1v.z, a1v.w};
            float bv[8] = {bv0.x, bv0.y, bv0.z, bv0.w, bv1.x, bv1.y, bv1.z, bv1.w};
#pragma unroll
            for (int i = 0; i < 8; i++)
#pragma unroll
                for (int j = 0; j < 8; j++) acc[i][j] = fmaf(av[i], bv[j], acc[i][j]);
        }
        if (more) {
            int nb = buf ^ 1;
            As[nb][a_k4 + 0][a_row] = pa.x;
            As[nb][a_k4 + 1][a_row] = pa.y;
            As[nb][a_k4 + 2][a_row] = pa.z;
            As[nb][a_k4 + 3][a_row] = pa.w;
            *(float4*)&Bs[nb][b_k][b_n4] = pb;
        }
        __syncthreads();
    }

#pragma unroll
    for (int i = 0; i < 8; i++) {
        int m = row0 + ty * 8 + i;
        int b = m >> 11;
        float mk = mask[m];
#pragma unroll
        for (int j = 0; j < 8; j++) {
            int n = col0 + tx * 8 + j;
            dst[(size_t)m * OUTD + n] = mk * (acc[i][j] + hb[b * OUTD + n]) + bias[n];
        }
    }
}

// batched Adj = e1 @ e2^T, raw values to out; fused per-batch min
__global__ __launch_bounds__(256, 2) void k_gemm2(float* __restrict__ out) {
    __shared__ float As[2][BK2][BM];
    __shared__ float Bs[2][BK2][BN];
    __shared__ unsigned int sMin;
    int b = blockIdx.z;
    int bn = blockIdx.x, bm = blockIdx.y;
    int tid = threadIdx.x;
    int tx = tid % 16, ty = tid / 16;
    int row0 = bm * BM, col0 = bn * BN;
    const float* e1p = g_e1 + (size_t)b * NN * OUTD;
    const float* e2p = g_e2 + (size_t)b * NN * OUTD;

    int a_row = tid >> 1;
    int a_k4 = (tid & 1) * 4;

    const float* agp = e1p + (size_t)(row0 + a_row) * OUTD + a_k4;
    const float* bgp = e2p + (size_t)(col0 + a_row) * OUTD + a_k4;

    if (tid == 0) sMin = 0xFFFFFFFFu;

    float acc[8][8];
#pragma unroll
    for (int i = 0; i < 8; i++)
#pragma unroll
        for (int j = 0; j < 8; j++) acc[i][j] = 0.f;

    {
        float4 pa = *(const float4*)agp;
        float4 pb = *(const float4*)bgp;
        As[0][a_k4 + 0][a_row] = pa.x;
        As[0][a_k4 + 1][a_row] = pa.y;
        As[0][a_k4 + 2][a_row] = pa.z;
        As[0][a_k4 + 3][a_row] = pa.w;
        Bs[0][a_k4 + 0][a_row] = pb.x;
        Bs[0][a_k4 + 1][a_row] = pb.y;
        Bs[0][a_k4 + 2][a_row] = pb.z;
        Bs[0][a_k4 + 3][a_row] = pb.w;
    }
    __syncthreads();

    for (int k0 = 0; k0 < OUTD; k0 += BK2) {
        int buf = (k0 >> 3) & 1;
        float4 pa, pb;
        bool more = (k0 + BK2) < OUTD;
        if (more) {
            pa = *(const float4*)(agp + k0 + BK2);
            pb = *(const float4*)(bgp + k0 + BK2);
        }
#pragma unroll
        for (int kk = 0; kk < BK2; kk++) {
            float4 a0 = *(const float4*)&As[buf][kk][ty * 8];
            float4 a1v = *(const float4*)&As[buf][kk][ty * 8 + 4];
            float4 bv0 = *(const float4*)&Bs[buf][kk][tx * 8];
            float4 bv1 = *(const float4*)&Bs[buf][kk][tx * 8 + 4];
            float av[8] = {a0.x, a0.y, a0.z, a0.w, a1v.x, a1v.y, a1v.z, a1v.w};
            float bv[8] = {bv0.x, bv0.y, bv0.z, bv0.w, bv1.x, bv1.y, bv1.z, bv1.w};
#pragma unroll
            for (int i = 0; i < 8; i++)
#pragma unroll
                for (int j = 0; j < 8; j++) acc[i][j] = fmaf(av[i], bv[j], acc[i][j]);
        }
        if (more) {
            int nb = buf ^ 1;
            As[nb][a_k4 + 0][a_row] = pa.x;
            As[nb][a_k4 + 1][a_row] = pa.y;
            As[nb][a_k4 + 2][a_row] = pa.z;
            As[nb][a_k4 + 3][a_row] = pa.w;
            Bs[nb][a_k4 + 0][a_row] = pb.x;
            Bs[nb][a_k4 + 1][a_row] = pb.y;
            Bs[nb][a_k4 + 2][a_row] = pb.z;
            Bs[nb][a_k4 + 3][a_row] = pb.w;
        }
        __syncthreads();
    }

    float lmin = 3.402823466e+38f;
    float* outb = out + (size_t)b * NN * NN;
#pragma unroll
    for (int i = 0; i < 8; i++) {
        int m = row0 + ty * 8 + i;
        float* op = outb + (size_t)m * NN + col0 + tx * 8;
        float4 v0 = make_float4(acc[i][0], acc[i][1], acc[i][2], acc[i][3]);
        float4 v1 = make_float4(acc[i][4], acc[i][5], acc[i][6], acc[i][7]);
        *(float4*)op = v0;
        *(float4*)(op + 4) = v1;
        lmin = fminf(lmin, fminf(fminf(fminf(v0.x, v0.y), fminf(v0.z, v0.w)),
                                 fminf(fminf(v1.x, v1.y), fminf(v1.z, v1.w))));
    }
#pragma unroll
    for (int off = 16; off > 0; off >>= 1)
        lmin = fminf(lmin, __shfl_xor_sync(0xFFFFFFFFu, lmin, off));
    if ((tid & 31) == 0) atomicMin(&sMin, fmap(lmin));
    __syncthreads();
    if (tid == 0) atomicMin(&g_minbits[b], sMin);
}

// pass 1: per-row radix select of the KTOP-th shifted value, tie count, rowsum -> d_i
#define RT 256
#define EPT 8
__global__ __launch_bounds__(RT) void k_sel(const float* __restrict__ out,
                                            const float* __restrict__ mask) {
    __shared__ unsigned int hist[256];
    __shared__ unsigned int warpsum[8];
    __shared__ unsigned int s_digit, s_r;
    __shared__ float s_part[8];

    int row = blockIdx.x;
    int b = row >> 11;
    int tid = threadIdx.x;
    int lane = tid & 31;
    int warp = tid >> 5;
    float minb = funmap(g_minbits[b]);
    float mk = mask[row];
    const float* rp = out + (size_t)row * NN;

    float v[EPT];
    unsigned int key[EPT];
    {
        float4 x0 = *(const float4*)(rp + tid * EPT);
        float4 x1 = *(const float4*)(rp + tid * EPT + 4);
        float xv[8] = {x0.x, x0.y, x0.z, x0.w, x1.x, x1.y, x1.z, x1.w};
#pragma unroll
        for (int q = 0; q < EPT; q++) {
            v[q] = (xv[q] - minb) * mk;
            key[q] = fmap(v[q]);
        }
    }

    unsigned int prefix = 0;
    unsigned int r = KTOP;
#pragma unroll
    for (int shift = 24; shift >= 0; shift -= 8) {
        hist[tid] = 0;
        __syncthreads();
        unsigned int pmask = (shift == 24) ? 0u : (0xFFFFFFFFu << (shift + 8));
#pragma unroll
        for (int q = 0; q < EPT; q++) {
            unsigned int k = key[q];
            bool match = ((k & pmask) == prefix);
            unsigned int d = match ? ((k >> shift) & 0xFFu) : 0xFFFFFFFFu;
            unsigned int peers = __match_any_sync(0xFFFFFFFFu, d);
            if (match && (lane == (__ffs(peers) - 1)))
                atomicAdd(&hist[d], __popc(peers));
        }
        __syncthreads();
        unsigned int h = hist[tid];
        unsigned int s = h;
#pragma unroll
        for (int off = 1; off < 32; off <<= 1) {
            unsigned int t = __shfl_down_sync(0xFFFFFFFFu, s, off);
            if (lane + off < 32) s += t;
        }
        if (lane == 0) warpsum[warp] = s;  // warp total (inclusive suffix at lane0)
        __syncthreads();
        unsigned int woff = 0;
#pragma unroll
        for (int w = 0; w < 8; w++)
            if (w > warp) woff += warpsum[w];
        unsigned int suffix = s + woff;  // sum over bins >= tid
        if (suffix >= r && suffix - h < r) {
            s_digit = (unsigned int)tid;
            s_r = r - (suffix - h);
        }
        __syncthreads();
        prefix |= (s_digit << shift);
        r = s_r;
    }
    unsigned int T = prefix;
    unsigned int eq_needed = r;

    // rowsum of kept values: strict-greater sum + eq_needed copies of the tie value
    float lsum = 0.f;
#pragma unroll
    for (int q = 0; q < EPT; q++)
        if (key[q] > T) lsum += v[q];
#pragma unroll
    for (int off = 16; off > 0; off >>= 1) lsum += __shfl_xor_sync(0xFFFFFFFFu, lsum, off);
    if (lane == 0) s_part[warp] = lsum;
    __syncthreads();
    if (tid == 0) {
        float tot = 0.f;
#pragma unroll
        for (int w = 0; w < 8; w++) tot += s_part[w];
        tot += (float)eq_needed * funmap(T);
        float d = (tot > 0.f) ? (1.0f / sqrtf(tot)) : 0.0f;
        g_dinv[row] = d;
        g_T[row] = T;
        g_eq[row] = eq_needed;
    }
}

// pass 2: apply topk mask with stable tie rank + d_i * v * d_j, streaming
__global__ __launch_bounds__(RT) void k_apply(float* __restrict__ out,
                                              const float* __restrict__ mask) {
    __shared__ unsigned int s_w[8];

    int row = blockIdx.x;
    int b = row >> 11;
    int tid = threadIdx.x;
    int lane = tid & 31;
    int warp = tid >> 5;
    float minb = funmap(g_minbits[b]);
    float mk = mask[row];
    unsigned int T = g_T[row];
    unsigned int eq = g_eq[row];
    float di = g_dinv[row];
    float* rp = out + (size_t)row * NN;

    float v[EPT];
    unsigned int key[EPT];
    {
        float4 x0 = *(const float4*)(rp + tid * EPT);
        float4 x1 = *(const float4*)(rp + tid * EPT + 4);
        float xv[8] = {x0.x, x0.y, x0.z, x0.w, x1.x, x1.y, x1.z, x1.w};
#pragma unroll
        for (int q = 0; q < EPT; q++) {
            v[q] = (xv[q] - minb) * mk;
            key[q] = fmap(v[q]);
        }
    }

    unsigned int cnt = 0;
#pragma unroll
    for (int q = 0; q < EPT; q++) cnt += (key[q] == T) ? 1u : 0u;
    // exclusive scan of cnt over 256 threads (warp scan + smem)
    unsigned int incl = cnt;
#pragma unroll
    for (int off = 1; off < 32; off <<= 1) {
        unsigned int t = __shfl_up_sync(0xFFFFFFFFu, incl, off);
        if (lane >= off) incl += t;
    }
    if (lane == 31) s_w[warp] = incl;
    __syncthreads();
    unsigned int woff = 0;
#pragma unroll
    for (int w = 0; w < 8; w++)
        if (w < warp) woff += s_w[w];
    unsigned int rank = woff + incl - cnt;

    float dj[EPT];
    {
        float4 d0 = *(const float4*)(g_dinv + ((size_t)b << 11) + tid * EPT);
        float4 d1 = *(const float4*)(g_dinv + ((size_t)b << 11) + tid * EPT + 4);
        dj[0] = d0.x; dj[1] = d0.y; dj[2] = d0.z; dj[3] = d0.w;
        dj[4] = d1.x; dj[5] = d1.y; dj[6] = d1.z; dj[7] = d1.w;
    }

    float o[EPT];
#pragma unroll
    for (int q = 0; q < EPT; q++) {
        unsigned int k = key[q];
        bool keep = (k > T) || (k == T && rank < eq);
        if (k == T) rank++;
        o[q] = keep ? (di * v[q]) * dj[q] : 0.0f;
    }
    float4 y0 = make_float4(o[0], o[1], o[2], o[3]);
    float4 y1 = make_float4(o[4], o[5], o[6], o[7]);
    *(float4*)(rp + tid * EPT) = y0;
    *(float4*)(rp + tid * EPT + 4) = y1;
}

extern "C" void kernel_launch(void* const* d_in, const int* in_sizes, int n_in,
                              void* d_out, int out_size) {
    const float* ge = (const float*)d_in[0];
    const float* mask = (const float*)d_in[1];
    const float* hs = (const float*)d_in[2];
    const float* W1 = (const float*)d_in[3];
    const float* b1 = (const float*)d_in[4];
    const float* W2 = (const float*)d_in[5];
    const float* b2 = (const float*)d_in[6];
    float* out = (float*)d_out;

    k_init<<<1, 32>>>();
    k_hb<<<BB, 512>>>(hs, W1, W2);
    k_gemm1<<<dim3(1024 / BN, (BB * NN) / BM), 256>>>(ge, mask, W1, b1, W2, b2);
    k_gemm2<<<dim3(NN / BN, NN / BM, BB), 256>>>(out);
    k_sel<<<BB * NN, RT>>>(out, mask);
    k_apply<<<BB * NN, RT>>>(out, mask);
}

// round 5
// speedup vs baseline: 1.2091x; 1.0525x over previous
#include <cuda_runtime.h>
#include <cstdint>

#define BB 16
#define NN 2048
#define DG 512
#define DH 512
#define OUTD 512
#define KTOP 512

// scratch (no cudaMalloc allowed)
__device__ float g_e1[BB * NN * OUTD];
__device__ float g_e2[BB * NN * OUTD];
__device__ float g_hb1[BB * OUTD];
__device__ float g_hb2[BB * OUTD];
__device__ unsigned int g_minbits[BB];
__device__ float g_dinv[BB * NN];
__device__ unsigned int g_T[BB * NN];
__device__ unsigned int g_eq[BB * NN];

__device__ __forceinline__ unsigned int fmap(float f) {
    unsigned int u = __float_as_uint(f);
    return (u & 0x80000000u) ? ~u : (u | 0x80000000u);
}
__device__ __forceinline__ float funmap(unsigned int m) {
    unsigned int u = (m & 0x80000000u) ? (m ^ 0x80000000u) : ~m;
    return __uint_as_float(u);
}

__global__ void k_init() {
    if (threadIdx.x < BB) g_minbits[threadIdx.x] = 0xFFFFFFFFu;
}

// per-batch hidden contribution: g_hb[b,o] = sum_d h[b,d] * W[512+d, o]
__global__ void k_hb(const float* __restrict__ hidden,
                     const float* __restrict__ W1,
                     const float* __restrict__ W2) {
    int b = blockIdx.x;
    int o = threadIdx.x;  // 512 threads
    const float* h = hidden + b * DH;
    float a1 = 0.f, a2 = 0.f;
#pragma unroll 4
    for (int d = 0; d < DH; d++) {
        float hv = h[d];
        a1 = fmaf(hv, W1[(size_t)(DG + d) * OUTD + o], a1);
        a2 = fmaf(hv, W2[(size_t)(DG + d) * OUTD + o], a2);
    }
    g_hb1[b * OUTD + o] = a1;
    g_hb2[b * OUTD + o] = a2;
}

#define BM 128
#define BN2 256
#define BK2 8
#define TM 16
#define TN 8

// e1/e2 GEMM: C[32768, 1024] = ge[32768,512] @ W[512,1024] (+ hb, bias, mask)
// 16x8 thread tile: 0.75 smem-bytes per FMA (crossbar no longer binding)
__global__ __launch_bounds__(256, 1) void k_gemm1(
    const float* __restrict__ ge, const float* __restrict__ mask,
    const float* __restrict__ W1, const float* __restrict__ b1,
    const float* __restrict__ W2, const float* __restrict__ b2) {
    __shared__ float As[2][BK2][BM];
    __shared__ float Bs[2][BK2][BN2];
    int bn = blockIdx.x;  // 0..3 over 1024 cols
    int bm = blockIdx.y;  // 0..255
    int tid = threadIdx.x;
    int tx = tid & 31;   // 32 col-groups of TN=8
    int ty = tid >> 5;   // 8 row-groups of TM=16
    int row0 = bm * BM;
    int col0 = (bn & 1) * BN2;

    const float* W;
    const float* bias;
    const float* hb;
    float* dst;
    if (bn < 2) {
        W = W1; bias = b1; hb = g_hb1; dst = g_e1;
    } else {
        W = W2; bias = b2; hb = g_hb2; dst = g_e2;
    }

    int a_row = tid >> 1;        // 0..127
    int a_k4 = (tid & 1) * 4;    // 0 or 4
    int b_k = tid >> 5;          // 0..7
    int b_n8 = (tid & 31) * 8;   // 0..248

    const float* agp = ge + (size_t)(row0 + a_row) * DG + a_k4;
    const float* bgp = W + (size_t)b_k * OUTD + col0 + b_n8;

    float acc[TM][TN];
#pragma unroll
    for (int i = 0; i < TM; i++)
#pragma unroll
        for (int j = 0; j < TN; j++) acc[i][j] = 0.f;

    {
        float4 pa = *(const float4*)agp;
        float4 pb0 = *(const float4*)bgp;
        float4 pb1 = *(const float4*)(bgp + 4);
        As[0][a_k4 + 0][a_row] = pa.x;
        As[0][a_k4 + 1][a_row] = pa.y;
        As[0][a_k4 + 2][a_row] = pa.z;
        As[0][a_k4 + 3][a_row] = pa.w;
        *(float4*)&Bs[0][b_k][b_n8] = pb0;
        *(float4*)&Bs[0][b_k][b_n8 + 4] = pb1;
    }
    __syncthreads();

    for (int k0 = 0; k0 < DG; k0 += BK2) {
        int buf = (k0 >> 3) & 1;
        float4 pa, pb0, pb1;
        bool more = (k0 + BK2) < DG;
        if (more) {
            pa = *(const float4*)(agp + k0 + BK2);
            pb0 = *(const float4*)(bgp + (size_t)(k0 + BK2) * OUTD);
            pb1 = *(const float4*)(bgp + (size_t)(k0 + BK2) * OUTD + 4);
        }
#pragma unroll
        for (int kk = 0; kk < BK2; kk++) {
            float4 a0 = *(const float4*)&As[buf][kk][ty * TM];
            float4 a1v = *(const float4*)&As[buf][kk][ty * TM + 4];
            float4 a2v = *(const float4*)&As[buf][kk][ty * TM + 8];
            float4 a3v = *(const float4*)&As[buf][kk][ty * TM + 12];
            float4 bv0 = *(const float4*)&Bs[buf][kk][tx * TN];
            float4 bv1 = *(const float4*)&Bs[buf][kk][tx * TN + 4];
            float av[TM] = {a0.x, a0.y, a0.z, a0.w, a1v.x, a1v.y, a1v.z, a1v.w,
                            a2v.x, a2v.y, a2v.z, a2v.w, a3v.x, a3v.y, a3v.z, a3v.w};
            float bv[TN] = {bv0.x, bv0.y, bv0.z, bv0.w, bv1.x, bv1.y, bv1.z, bv1.w};
#pragma unroll
            for (int i = 0; i < TM; i++)
#pragma unroll
                for (int j = 0; j < TN; j++) acc[i][j] = fmaf(av[i], bv[j], acc[i][j]);
        }
        if (more) {
            int nb = buf ^ 1;
            As[nb][a_k4 + 0][a_row] = pa.x;
            As[nb][a_k4 + 1][a_row] = pa.y;
            As[nb][a_k4 + 2][a_row] = pa.z;
            As[nb][a_k4 + 3][a_row] = pa.w;
            *(float4*)&Bs[nb][b_k][b_n8] = pb0;
            *(float4*)&Bs[nb][b_k][b_n8 + 4] = pb1;
        }
        __syncthreads();
    }

    int b = row0 >> 11;  // constant per block (2048 % 128 == 0)
    float hbn[TN], bnn[TN];
#pragma unroll
    for (int j = 0; j < TN; j++) {
        int n = col0 + tx * TN + j;
        hbn[j] = hb[b * OUTD + n];
        bnn[j] = bias[n];
    }
#pragma unroll
    for (int i = 0; i < TM; i++) {
        int m = row0 + ty * TM + i;
        float mk = mask[m];
        float* dp = dst + (size_t)m * OUTD + col0 + tx * TN;
        float o[TN];
#pragma unroll
        for (int j = 0; j < TN; j++) o[j] = mk * (acc[i][j] + hbn[j]) + bnn[j];
        *(float4*)dp = make_float4(o[0], o[1], o[2], o[3]);
        *(float4*)(dp + 4) = make_float4(o[4], o[5], o[6], o[7]);
    }
}

// batched Adj = e1 @ e2^T, raw values to out; fused per-batch min
__global__ __launch_bounds__(256, 1) void k_gemm2(float* __restrict__ out) {
    __shared__ float As[2][BK2][BM];
    __shared__ float Bs[2][BK2][BN2];
    __shared__ unsigned int sMin;
    int b = blockIdx.z;
    int bn = blockIdx.x, bm = blockIdx.y;
    int tid = threadIdx.x;
    int tx = tid & 31;
    int ty = tid >> 5;
    int row0 = bm * BM, col0 = bn * BN2;
    const float* e1p = g_e1 + (size_t)b * NN * OUTD;
    const float* e2p = g_e2 + (size_t)b * NN * OUTD;

    int a_row = tid >> 1;
    int a_k4 = (tid & 1) * 4;

    const float* agp = e1p + (size_t)(row0 + a_row) * OUTD + a_k4;
    const float* bgp = e2p + (size_t)(col0 + tid) * OUTD;  // one e2 row per thread

    if (tid == 0) sMin = 0xFFFFFFFFu;

    float acc[TM][TN];
#pragma unroll
    for (int i = 0; i < TM; i++)
#pragma unroll
        for (int j = 0; j < TN; j++) acc[i][j] = 0.f;

    {
        float4 pa = *(const float4*)agp;
        float4 pb0 = *(const float4*)bgp;
        float4 pb1 = *(const float4*)(bgp + 4);
        As[0][a_k4 + 0][a_row] = pa.x;
        As[0][a_k4 + 1][a_row] = pa.y;
        As[0][a_k4 + 2][a_row] = pa.z;
        As[0][a_k4 + 3][a_row] = pa.w;
        Bs[0][0][tid] = pb0.x;
        Bs[0][1][tid] = pb0.y;
        Bs[0][2][tid] = pb0.z;
        Bs[0][3][tid] = pb0.w;
        Bs[0][4][tid] = pb1.x;
        Bs[0][5][tid] = pb1.y;
        Bs[0][6][tid] = pb1.z;
        Bs[0][7][tid] = pb1.w;
    }
    __syncthreads();

    for (int k0 = 0; k0 < OUTD; k0 += BK2) {
        int buf = (k0 >> 3) & 1;
        float4 pa, pb0, pb1;
        bool more = (k0 + BK2) < OUTD;
        if (more) {
            pa = *(const float4*)(agp + k0 + BK2);
            pb0 = *(const float4*)(bgp + k0 + BK2);
            pb1 = *(const float4*)(bgp + k0 + BK2 + 4);
        }
#pragma unroll
        for (int kk = 0; kk < BK2; kk++) {
            float4 a0 = *(const float4*)&As[buf][kk][ty * TM];
            float4 a1v = *(const float4*)&As[buf][kk][ty * TM + 4];
            float4 a2v = *(const float4*)&As[buf][kk][ty * TM + 8];
            float4 a3v = *(const float4*)&As[buf][kk][ty * TM + 12];
            float4 bv0 = *(const float4*)&Bs[buf][kk][tx * TN];
            float4 bv1 = *(const float4*)&Bs[buf][kk][tx * TN + 4];
            float av[TM] = {a0.x, a0.y, a0.z, a0.w, a1v.x, a1v.y, a1v.z, a1v.w,
                            a2v.x, a2v.y, a2v.z, a2v.w, a3v.x, a3v.y, a3v.z, a3v.w};
            float bv[TN] = {bv0.x, bv0.y, bv0.z, bv0.w, bv1.x, bv1.y, bv1.z, bv1.w};
#pragma unroll
            for (int i = 0; i < TM; i++)
#pragma unroll
                for (int j = 0; j < TN; j++) acc[i][j] = fmaf(av[i], bv[j], acc[i][j]);
        }
        if (more) {
            int nb = buf ^ 1;
            As[nb][a_k4 + 0][a_row] = pa.x;
            As[nb][a_k4 + 1][a_row] = pa.y;
            As[nb][a_k4 + 2][a_row] = pa.z;
            As[nb][a_k4 + 3][a_row] = pa.w;
            Bs[nb][0][tid] = pb0.x;
            Bs[nb][1][tid] = pb0.y;
            Bs[nb][2][tid] = pb0.z;
            Bs[nb][3][tid] = pb0.w;
            Bs[nb][4][tid] = pb1.x;
            Bs[nb][5][tid] = pb1.y;
            Bs[nb][6][tid] = pb1.z;
            Bs[nb][7][tid] = pb1.w;
        }
        __syncthreads();
    }

    float lmin = 3.402823466e+38f;
    float* outb = out + (size_t)b * NN * NN;
#pragma unroll
    for (int i = 0; i < TM; i++) {
        int m = row0 + ty * TM + i;
        float* op = outb + (size_t)m * NN + col0 + tx * TN;
        float4 v0 = make_float4(acc[i][0], acc[i][1], acc[i][2], acc[i][3]);
        float4 v1 = make_float4(acc[i][4], acc[i][5], acc[i][6], acc[i][7]);
        *(float4*)op = v0;
        *(float4*)(op + 4) = v1;
        lmin = fminf(lmin, fminf(fminf(fminf(v0.x, v0.y), fminf(v0.z, v0.w)),
                                 fminf(fminf(v1.x, v1.y), fminf(v1.z, v1.w))));
    }
#pragma unroll
    for (int off = 16; off > 0; off >>= 1)
        lmin = fminf(lmin, __shfl_xor_sync(0xFFFFFFFFu, lmin, off));
    if ((tid & 31) == 0) atomicMin(&sMin, fmap(lmin));
    __syncthreads();
    if (tid == 0) atomicMin(&g_minbits[b], sMin);
}

// pass 1: per-row radix select of the KTOP-th shifted value, tie count, rowsum -> d_i
#define RT 256
#define EPT 8
__global__ __launch_bounds__(RT) void k_sel(const float* __restrict__ out,
                                            const float* __restrict__ mask) {
    __shared__ unsigned int hist[256];
    __shared__ unsigned int warpsum[8];
    __shared__ unsigned int s_digit, s_r;
    __shared__ float s_part[8];

    int row = blockIdx.x;
    int b = row >> 11;
    int tid = threadIdx.x;
    int lane = tid & 31;
    int warp = tid >> 5;
    float minb = funmap(g_minbits[b]);
    float mk = mask[row];
    const float* rp = out + (size_t)row * NN;

    float v[EPT];
    unsigned int key[EPT];
    {
        float4 x0 = *(const float4*)(rp + tid * EPT);
        float4 x1 = *(const float4*)(rp + tid * EPT + 4);
        float xv[8] = {x0.x, x0.y, x0.z, x0.w, x1.x, x1.y, x1.z, x1.w};
#pragma unroll
        for (int q = 0; q < EPT; q++) {
            v[q] = (xv[q] - minb) * mk;
            key[q] = fmap(v[q]);
        }
    }

    unsigned int prefix = 0;
    unsigned int r = KTOP;
#pragma unroll
    for (int shift = 24; shift >= 0; shift -= 8) {
        hist[tid] = 0;
        __syncthreads();
        unsigned int pmask = (shift == 24) ? 0u : (0xFFFFFFFFu << (shift + 8));
#pragma unroll
        for (int q = 0; q < EPT; q++) {
            unsigned int k = key[q];
            bool match = ((k & pmask) == prefix);
            unsigned int d = match ? ((k >> shift) & 0xFFu) : 0xFFFFFFFFu;
            unsigned int peers = __match_any_sync(0xFFFFFFFFu, d);
            if (match && (lane == (__ffs(peers) - 1)))
                atomicAdd(&hist[d], __popc(peers));
        }
        __syncthreads();
        unsigned int h = hist[tid];
        unsigned int s = h;
#pragma unroll
        for (int off = 1; off < 32; off <<= 1) {
            unsigned int t = __shfl_down_sync(0xFFFFFFFFu, s, off);
            if (lane + off < 32) s += t;
        }
        if (lane == 0) warpsum[warp] = s;
        __syncthreads();
        unsigned int woff = 0;
#pragma unroll
        for (int w = 0; w < 8; w++)
            if (w > warp) woff += warpsum[w];
        unsigned int suffix = s + woff;  // sum over bins >= tid
        if (suffix >= r && suffix - h < r) {
            s_digit = (unsigned int)tid;
            s_r = r - (suffix - h);
        }
        __syncthreads();
        prefix |= (s_digit << shift);
        r = s_r;
    }
    unsigned int T = prefix;
    unsigned int eq_needed = r;

    float lsum = 0.f;
#pragma unroll
    for (int q = 0; q < EPT; q++)
        if (key[q] > T) lsum += v[q];
#pragma unroll
    for (int off = 16; off > 0; off >>= 1) lsum += __shfl_xor_sync(0xFFFFFFFFu, lsum, off);
    if (lane == 0) s_part[warp] = lsum;
    __syncthreads();
    if (tid == 0) {
        float tot = 0.f;
#pragma unroll
        for (int w = 0; w < 8; w++) tot += s_part[w];
        tot += (float)eq_needed * funmap(T);
        float d = (tot > 0.f) ? (1.0f / sqrtf(tot)) : 0.0f;
        g_dinv[row] = d;
        g_T[row] = T;
        g_eq[row] = eq_needed;
    }
}

// pass 2: apply topk mask with stable tie rank + d_i * v * d_j, streaming
__global__ __launch_bounds__(RT) void k_apply(float* __restrict__ out,
                                              const float* __restrict__ mask) {
    __shared__ unsigned int s_w[8];

    int row = blockIdx.x;
    int b = row >> 11;
    int tid = threadIdx.x;
    int lane = tid & 31;
    int warp = tid >> 5;
    float minb = funmap(g_minbits[b]);
    float mk = mask[row];
    unsigned int T = g_T[row];
    unsigned int eq = g_eq[row];
    float di = g_dinv[row];
    float* rp = out + (size_t)row * NN;

    float v[EPT];
    unsigned int key[EPT];
    {
        float4 x0 = *(const float4*)(rp + tid * EPT);
        float4 x1 = *(const float4*)(rp + tid * EPT + 4);
        float xv[8] = {x0.x, x0.y, x0.z, x0.w, x1.x, x1.y, x1.z, x1.w};
#pragma unroll
        for (int q = 0; q < EPT; q++) {
            v[q] = (xv[q] - minb) * mk;
            key[q] = fmap(v[q]);
        }
    }

    unsigned int cnt = 0;
#pragma unroll
    for (int q = 0; q < EPT; q++) cnt += (key[q] == T) ? 1u : 0u;
    unsigned int incl = cnt;
#pragma unroll
    for (int off = 1; off < 32; off <<= 1) {
        unsigned int t = __shfl_up_sync(0xFFFFFFFFu, incl, off);
        if (lane >= off) incl += t;
    }
    if (lane == 31) s_w[warp] = incl;
    __syncthreads();
    unsigned int woff = 0;
#pragma unroll
    for (int w = 0; w < 8; w++)
        if (w < warp) woff += s_w[w];
    unsigned int rank = woff + incl - cnt;

    float dj[EPT];
    {
        float4 d0 = *(const float4*)(g_dinv + ((size_t)b << 11) + tid * EPT);
        float4 d1 = *(const float4*)(g_dinv + ((size_t)b << 11) + tid * EPT + 4);
        dj[0] = d0.x; dj[1] = d0.y; dj[2] = d0.z; dj[3] = d0.w;
        dj[4] = d1.x; dj[5] = d1.y; dj[6] = d1.z; dj[7] = d1.w;
    }

    float o[EPT];
#pragma unroll
    for (int q = 0; q < EPT; q++) {
        unsigned int k = key[q];
        bool keep = (k > T) || (k == T && rank < eq);
        if (k == T) rank++;
        o[q] = keep ? (di * v[q]) * dj[q] : 0.0f;
    }
    float4 y0 = make_float4(o[0], o[1], o[2], o[3]);
    float4 y1 = make_float4(o[4], o[5], o[6], o[7]);
    *(float4*)(rp + tid * EPT) = y0;
    *(float4*)(rp + tid * EPT + 4) = y1;
}

extern "C" void kernel_launch(void* const* d_in, const int* in_sizes, int n_in,
                              void* d_out, int out_size) {
    const float* ge = (const float*)d_in[0];
    const float* mask = (const float*)d_in[1];
    const float* hs = (const float*)d_in[2];
    const float* W1 = (const float*)d_in[3];
    const float* b1 = (const float*)d_in[4];
    const float* W2 = (const float*)d_in[5];
    const float* b2 = (const float*)d_in[6];
    float* out = (float*)d_out;

    k_init<<<1, 32>>>();
    k_hb<<<BB, 512>>>(hs, W1, W2);
    k_gemm1<<<dim3(4, (BB * NN) / BM), 256>>>(ge, mask, W1, b1, W2, b2);
    k_gemm2<<<dim3(NN / BN2, NN / BM, BB), 256>>>(out);
    k_sel<<<BB * NN, RT>>>(out, mask);
    k_apply<<<BB * NN, RT>>>(out, mask);
}

// round 8
// speedup vs baseline: 1.2961x; 1.0720x over previous
#include <cuda_runtime.h>
#include <cuda_bf16.h>
#include <cstdint>

#define BB 16
#define NN 2048
#define DG 512
#define DH 512
#define OUTD 512
#define KTOP 512

// ---------------- scratch (no cudaMalloc allowed) ----------------
__device__ float g_hb1[BB * OUTD];
__device__ float g_hb2[BB * OUTD];
__device__ unsigned int g_minbits[BB];
__device__ float g_dinv[BB * NN];
__device__ unsigned int g_T[BB * NN];
__device__ unsigned int g_eq[BB * NN];
// bf16 3-way split planes of e1 (A) and e2 (B)
__device__ __nv_bfloat16 g_a0[BB * NN * OUTD];
__device__ __nv_bfloat16 g_a1[BB * NN * OUTD];
__device__ __nv_bfloat16 g_a2[BB * NN * OUTD];
__device__ __nv_bfloat16 g_b0[BB * NN * OUTD];
__device__ __nv_bfloat16 g_b1[BB * NN * OUTD];
__device__ __nv_bfloat16 g_b2[BB * NN * OUTD];

__device__ __forceinline__ unsigned int fmap(float f) {
    unsigned int u = __float_as_uint(f);
    return (u & 0x80000000u) ? ~u : (u | 0x80000000u);
}
__device__ __forceinline__ float funmap(unsigned int m) {
    unsigned int u = (m & 0x80000000u) ? (m ^ 0x80000000u) : ~m;
    return __uint_as_float(u);
}
__device__ __forceinline__ uint32_t smem_u32(const void* p) {
    uint32_t a;
    asm("{ .reg .u64 t; cvta.to.shared.u64 t, %1; cvt.u32.u64 %0, t; }" : "=r"(a) : "l"(p));
    return a;
}
__device__ __forceinline__ void ldsm4(uint32_t* r, uint32_t addr) {
    asm volatile("ldmatrix.sync.aligned.m8n8.x4.shared.b16 {%0,%1,%2,%3}, [%4];"
                 : "=r"(r[0]), "=r"(r[1]), "=r"(r[2]), "=r"(r[3]) : "r"(addr));
}
__device__ __forceinline__ void mma_bf16(float* c, const uint32_t* a, uint32_t b0, uint32_t b1) {
    asm volatile(
        "mma.sync.aligned.m16n8k16.row.col.f32.bf16.bf16.f32 "
        "{%0,%1,%2,%3}, {%4,%5,%6,%7}, {%8,%9}, {%0,%1,%2,%3};"
        : "+f"(c[0]), "+f"(c[1]), "+f"(c[2]), "+f"(c[3])
        : "r"(a[0]), "r"(a[1]), "r"(a[2]), "r"(a[3]), "r"(b0), "r"(b1));
}
__device__ __forceinline__ void cp16(uint32_t saddr, const void* g) {
    asm volatile("cp.async.cg.shared.global [%0], [%1], 16;" :: "r"(saddr), "l"(g));
}
#define CP_COMMIT() asm volatile("cp.async.commit_group;" ::: "memory")
#define CP_WAIT1() asm volatile("cp.async.wait_group 1;" ::: "memory")
#define CP_WAIT0() asm volatile("cp.async.wait_group 0;" ::: "memory")

__global__ void k_init() {
    if (threadIdx.x < BB) g_minbits[threadIdx.x] = 0xFFFFFFFFu;
}

// per-batch hidden contribution
__global__ void k_hb(const float* __restrict__ hidden,
                     const float* __restrict__ W1,
                     const float* __restrict__ W2) {
    int b = blockIdx.x;
    int o = threadIdx.x;
    const float* h = hidden + b * DH;
    float a1 = 0.f, a2 = 0.f;
#pragma unroll 4
    for (int d = 0; d < DH; d++) {
        float hv = h[d];
        a1 = fmaf(hv, W1[(size_t)(DG + d) * OUTD + o], a1);
        a2 = fmaf(hv, W2[(size_t)(DG + d) * OUTD + o], a2);
    }
    g_hb1[b * OUTD + o] = a1;
    g_hb2[b * OUTD + o] = a2;
}

#define BM 128
#define BN2 256
#define BK2 8
#define TM 16
#define TN 8

// e1/e2 GEMM (SIMT fp32, bitwise-sequential K) with fused bf16 3-way split epilogue
__global__ __launch_bounds__(256, 1) void k_gemm1(
    const float* __restrict__ ge, const float* __restrict__ mask,
    const float* __restrict__ W1, const float* __restrict__ b1,
    const float* __restrict__ W2, const float* __restrict__ b2) {
    __shared__ float As[2][BK2][BM];
    __shared__ float Bs[2][BK2][BN2];
    int bn = blockIdx.x;
    int bm = blockIdx.y;
    int tid = threadIdx.x;
    int tx = tid & 31;
    int ty = tid >> 5;
    int row0 = bm * BM;
    int col0 = (bn & 1) * BN2;

    const float* W;
    const float* bias;
    const float* hb;
    __nv_bfloat16 *P0, *P1, *P2;
    if (bn < 2) {
        W = W1; bias = b1; hb = g_hb1;
        P0 = g_a0; P1 = g_a1; P2 = g_a2;
    } else {
        W = W2; bias = b2; hb = g_hb2;
        P0 = g_b0; P1 = g_b1; P2 = g_b2;
    }

    int a_row = tid >> 1;
    int a_k4 = (tid & 1) * 4;
    int b_k = tid >> 5;
    int b_n8 = (tid & 31) * 8;

    const float* agp = ge + (size_t)(row0 + a_row) * DG + a_k4;
    const float* bgp = W + (size_t)b_k * OUTD + col0 + b_n8;

    float acc[TM][TN];
#pragma unroll
    for (int i = 0; i < TM; i++)
#pragma unroll
        for (int j = 0; j < TN; j++) acc[i][j] = 0.f;

    {
        float4 pa = *(const float4*)agp;
        float4 pb0 = *(const float4*)bgp;
        float4 pb1 = *(const float4*)(bgp + 4);
        As[0][a_k4 + 0][a_row] = pa.x;
        As[0][a_k4 + 1][a_row] = pa.y;
        As[0][a_k4 + 2][a_row] = pa.z;
        As[0][a_k4 + 3][a_row] = pa.w;
        *(float4*)&Bs[0][b_k][b_n8] = pb0;
        *(float4*)&Bs[0][b_k][b_n8 + 4] = pb1;
    }
    __syncthreads();

    for (int k0 = 0; k0 < DG; k0 += BK2) {
        int buf = (k0 >> 3) & 1;
        float4 pa, pb0, pb1;
        bool more = (k0 + BK2) < DG;
        if (more) {
            pa = *(const float4*)(agp + k0 + BK2);
            pb0 = *(const float4*)(bgp + (size_t)(k0 + BK2) * OUTD);
            pb1 = *(const float4*)(bgp + (size_t)(k0 + BK2) * OUTD + 4);
        }
#pragma unroll
        for (int kk = 0; kk < BK2; kk++) {
            float4 a0 = *(const float4*)&As[buf][kk][ty * TM];
            float4 a1v = *(const float4*)&As[buf][kk][ty * TM + 4];
            float4 a2v = *(const float4*)&As[buf][kk][ty * TM + 8];
            float4 a3v = *(const float4*)&As[buf][kk][ty * TM + 12];
            float4 bv0 = *(const float4*)&Bs[buf][kk][tx * TN];
            float4 bv1 = *(const float4*)&Bs[buf][kk][tx * TN + 4];
            float av[TM] = {a0.x, a0.y, a0.z, a0.w, a1v.x, a1v.y, a1v.z, a1v.w,
                            a2v.x, a2v.y, a2v.z, a2v.w, a3v.x, a3v.y, a3v.z, a3v.w};
            float bv[TN] = {bv0.x, bv0.y, bv0.z, bv0.w, bv1.x, bv1.y, bv1.z, bv1.w};
#pragma unroll
            for (int i = 0; i < TM; i++)
#pragma unroll
                for (int j = 0; j < TN; j++) acc[i][j] = fmaf(av[i], bv[j], acc[i][j]);
        }
        if (more) {
            int nb = buf ^ 1;
            As[nb][a_k4 + 0][a_row] = pa.x;
            As[nb][a_k4 + 1][a_row] = pa.y;
            As[nb][a_k4 + 2][a_row] = pa.z;
            As[nb][a_k4 + 3][a_row] = pa.w;
            *(float4*)&Bs[nb][b_k][b_n8] = pb0;
            *(float4*)&Bs[nb][b_k][b_n8 + 4] = pb1;
        }
        __syncthreads();
    }

    int b = row0 >> 11;
    float hbn[TN], bnn[TN];
#pragma unroll
    for (int j = 0; j < TN; j++) {
        int n = col0 + tx * TN + j;
        hbn[j] = hb[b * OUTD + n];
        bnn[j] = bias[n];
    }
#pragma unroll
    for (int i = 0; i < TM; i++) {
        int m = row0 + ty * TM + i;
        float mk = mask[m];
        size_t base = (size_t)m * OUTD + col0 + tx * TN;
        __nv_bfloat16 hh[TN], mm_[TN], ll[TN];
#pragma unroll
        for (int j = 0; j < TN; j++) {
            float o = mk * (acc[i][j] + hbn[j]) + bnn[j];
            __nv_bfloat16 h = __float2bfloat16_rn(o);
            float r = o - __bfloat162float(h);
            __nv_bfloat16 md = __float2bfloat16_rn(r);
            float r2 = r - __bfloat162float(md);
            hh[j] = h;
            mm_[j] = md;
            ll[j] = __float2bfloat16_rn(r2);
        }
        *(uint4*)(P0 + base) = *(uint4*)hh;
        *(uint4*)(P1 + base) = *(uint4*)mm_;
        *(uint4*)(P2 + base) = *(uint4*)ll;
    }
}

// ---------------- tensor-core gemm2 (6-term bf16 split + per-k-step Kahan) ----------------
#define KC 32
#define ST 40                      // padded row stride in bf16 elems (80B)
#define PL (128 * ST)              // elems per plane tile
#define BUFE (6 * PL)              // elems per buffer
#define SMEMB (2 * BUFE * 2)       // bytes, two buffers
#define NCHK (OUTD / KC)           // 16

__global__ __launch_bounds__(256, 1) void k_gemm2m(float* __restrict__ out) {
    extern __shared__ __nv_bfloat16 sm[];
    __shared__ unsigned int sMin;
    int tid = threadIdx.x;
    int wid = tid >> 5;
    int lane = tid & 31;
    int b = blockIdx.z;
    int row0 = blockIdx.y * 128;
    int col0 = blockIdx.x * 128;
    int wm = wid >> 2;  // 0..1
    int wn = wid & 3;   // 0..3

    if (tid == 0) sMin = 0xFFFFFFFFu;

    // loader geometry: idx = tid + 256*it -> plane p = it>>1, row = (tid>>2) + 64*(it&1), g = tid&3
    int lrow = tid >> 2;     // 0..63
    int lg = (tid & 3) * 8;  // bf16 elem offset within 32-elem chunk row
    size_t rbaseA = ((size_t)(b << 11) + row0 + lrow) * OUTD + lg;
    size_t rbaseB = ((size_t)(b << 11) + col0 + lrow) * OUTD + lg;
    uint32_t smb = smem_u32(sm);
    uint32_t swbase = smb + (uint32_t)(lrow * ST + lg) * 2;

#define LOAD_CHUNK(kk0, bufsel)                                                          \
    do {                                                                                 \
        uint32_t sb_ = swbase + (uint32_t)(bufsel) * (BUFE * 2);                         \
        size_t ro_ = (size_t)64 * OUTD;                                                  \
        cp16(sb_ + 0 * (PL * 2), g_a0 + rbaseA + (kk0));                                 \
        cp16(sb_ + 0 * (PL * 2) + 64 * (ST * 2), g_a0 + rbaseA + ro_ + (kk0));           \
        cp16(sb_ + 1 * (PL * 2), g_a1 + rbaseA + (kk0));                                 \
        cp16(sb_ + 1 * (PL * 2) + 64 * (ST * 2), g_a1 + rbaseA + ro_ + (kk0));           \
        cp16(sb_ + 2 * (PL * 2), g_a2 + rbaseA + (kk0));                                 \
        cp16(sb_ + 2 * (PL * 2) + 64 * (ST * 2), g_a2 + rbaseA + ro_ + (kk0));           \
        cp16(sb_ + 3 * (PL * 2), g_b0 + rbaseB + (kk0));                                 \
        cp16(sb_ + 3 * (PL * 2) + 64 * (ST * 2), g_b0 + rbaseB + ro_ + (kk0));           \
        cp16(sb_ + 4 * (PL * 2), g_b1 + rbaseB + (kk0));                                 \
        cp16(sb_ + 4 * (PL * 2) + 64 * (ST * 2), g_b1 + rbaseB + ro_ + (kk0));           \
        cp16(sb_ + 5 * (PL * 2), g_b2 + rbaseB + (kk0));                                 \
        cp16(sb_ + 5 * (PL * 2) + 64 * (ST * 2), g_b2 + rbaseB + ro_ + (kk0));           \
        CP_COMMIT();                                                                     \
    } while (0)

    float sum[4][4][4], comp[4][4][4];
#pragma unroll
    for (int mf = 0; mf < 4; mf++)
#pragma unroll
        for (int nf = 0; nf < 4; nf++)
#pragma unroll
            for (int q = 0; q < 4; q++) {
                sum[mf][nf][q] = 0.f;
                comp[mf][nf][q] = 0.f;
            }

    const int pa_s[6] = {0, 0, 1, 0, 1, 2};
    const int pb_s[6] = {0, 1, 0, 2, 1, 0};

    LOAD_CHUNK(0, 0);

    for (int c = 0; c < NCHK; c++) {
        int buf = c & 1;
        uint32_t base = smb + buf * (BUFE * 2);
        bool more = (c + 1) < NCHK;
        if (more) {
            LOAD_CHUNK((c + 1) * KC, buf ^ 1);
            CP_WAIT1();
        } else {
            CP_WAIT0();
        }
        __syncthreads();

#pragma unroll
        for (int s = 0; s < 2; s++) {
            uint32_t afr[3][4][4];
            uint32_t bfr[3][2][4];
            {
                int arow = wm * 64 + (lane & 15);
                int acol = s * 16 + (lane >> 4) * 8;
#pragma unroll
                for (int p = 0; p < 3; p++)
#pragma unroll
                    for (int mf = 0; mf < 4; mf++)
                        ldsm4(afr[p][mf],
                              base + (uint32_t)(p * PL + (arow + mf * 16) * ST + acol) * 2);
                int nrow = wn * 32 + (lane & 7) + ((lane >> 4) & 1) * 8;
                int kcol = s * 16 + ((lane >> 3) & 1) * 8;
#pragma unroll
                for (int p = 0; p < 3; p++)
#pragma unroll
                    for (int g = 0; g < 2; g++)
                        ldsm4(bfr[p][g],
                              base + (uint32_t)((3 + p) * PL + (nrow + g * 16) * ST + kcol) * 2);
            }
#pragma unroll
            for (int mf = 0; mf < 4; mf++)
#pragma unroll
                for (int nf = 0; nf < 4; nf++) {
                    float a4[4] = {0.f, 0.f, 0.f, 0.f};
#pragma unroll
                    for (int t = 0; t < 6; t++)
                        mma_bf16(a4, afr[pa_s[t]][mf],
                                 bfr[pb_s[t]][nf >> 1][(nf & 1) * 2],
                                 bfr[pb_s[t]][nf >> 1][(nf & 1) * 2 + 1]);
                    // Kahan fold (rounding-exact intrinsics; optimizer-proof)
#pragma unroll
                    for (int q = 0; q < 4; q++) {
                        float y = __fsub_rn(a4[q], comp[mf][nf][q]);
                        float t2 = __fadd_rn(sum[mf][nf][q], y);
                        comp[mf][nf][q] = __fsub_rn(__fsub_rn(t2, sum[mf][nf][q]), y);
                        sum[mf][nf][q] = t2;
                    }
                }
        }
        __syncthreads();
    }

    // epilogue: write + fused per-batch min (value = sum - comp, final Kahan correction)
    float lmin = 3.402823466e+38f;
    float* outb = out + (size_t)b * NN * NN;
#pragma unroll
    for (int mf = 0; mf < 4; mf++)
#pragma unroll
        for (int nf = 0; nf < 4; nf++) {
            int r = row0 + wm * 64 + mf * 16 + (lane >> 2);
            int cc = col0 + wn * 32 + nf * 8 + (lane & 3) * 2;
            float v0x = __fsub_rn(sum[mf][nf][0], comp[mf][nf][0]);
            float v0y = __fsub_rn(sum[mf][nf][1], comp[mf][nf][1]);
            float v1x = __fsub_rn(sum[mf][nf][2], comp[mf][nf][2]);
            float v1y = __fsub_rn(sum[mf][nf][3], comp[mf][nf][3]);
            *(float2*)(outb + (size_t)r * NN + cc) = make_float2(v0x, v0y);
            *(float2*)(outb + (size_t)(r + 8) * NN + cc) = make_float2(v1x, v1y);
            lmin = fminf(lmin, fminf(fminf(v0x, v0y), fminf(v1x, v1y)));
        }
#pragma unroll
    for (int off = 16; off > 0; off >>= 1)
        lmin = fminf(lmin, __shfl_xor_sync(0xFFFFFFFFu, lmin, off));
    __syncthreads();
    if (lane == 0) atomicMin(&sMin, fmap(lmin));
    __syncthreads();
    if (tid == 0) atomicMin(&g_minbits[b], sMin);
}

// ---------------- selection / apply (unchanged) ----------------
#define RT 256
#define EPT 8
__global__ __launch_bounds__(RT) void k_sel(const float* __restrict__ out,
                                            const float* __restrict__ mask) {
    __shared__ unsigned int hist[256];
    __shared__ unsigned int warpsum[8];
    __shared__ unsigned int s_digit, s_r;
    __shared__ float s_part[8];

    int row = blockIdx.x;
    int b = row >> 11;
    int tid = threadIdx.x;
    int lane = tid & 31;
    int warp = tid >> 5;
    float minb = funmap(g_minbits[b]);
    float mk = mask[row];
    const float* rp = out + (size_t)row * NN;

    float v[EPT];
    unsigned int key[EPT];
    {
        float4 x0 = *(const float4*)(rp + tid * EPT);
        float4 x1 = *(const float4*)(rp + tid * EPT + 4);
        float xv[8] = {x0.x, x0.y, x0.z, x0.w, x1.x, x1.y, x1.z, x1.w};
#pragma unroll
        for (int q = 0; q < EPT; q++) {
            v[q] = (xv[q] - minb) * mk;
            key[q] = fmap(v[q]);
        }
    }

    unsigned int prefix = 0;
    unsigned int r = KTOP;
#pragma unroll
    for (int shift = 24; shift >= 0; shift -= 8) {
        hist[tid] = 0;
        __syncthreads();
        unsigned int pmask = (shift == 24) ? 0u : (0xFFFFFFFFu << (shift + 8));
#pragma unroll
        for (int q = 0; q < EPT; q++) {
            unsigned int k = key[q];
            bool match = ((k & pmask) == prefix);
            unsigned int d = match ? ((k >> shift) & 0xFFu) : 0xFFFFFFFFu;
            unsigned int peers = __match_any_sync(0xFFFFFFFFu, d);
            if (match && (lane == (__ffs(peers) - 1)))
                atomicAdd(&hist[d], __popc(peers));
        }
        __syncthreads();
        unsigned int h = hist[tid];
        unsigned int s = h;
#pragma unroll
        for (int off = 1; off < 32; off <<= 1) {
            unsigned int t = __shfl_down_sync(0xFFFFFFFFu, s, off);
            if (lane + off < 32) s += t;
        }
        if (lane == 0) warpsum[warp] = s;
        __syncthreads();
        unsigned int woff = 0;
#pragma unroll
        for (int w = 0; w < 8; w++)
            if (w > warp) woff += warpsum[w];
        unsigned int suffix = s + woff;
        if (suffix >= r && suffix - h < r) {
            s_digit = (unsigned int)tid;
            s_r = r - (suffix - h);
        }
        __syncthreads();
        prefix |= (s_digit << shift);
        r = s_r;
    }
    unsigned int T = prefix;
    unsigned int eq_needed = r;

    float lsum = 0.f;
#pragma unroll
    for (int q = 0; q < EPT; q++)
        if (key[q] > T) lsum += v[q];
#pragma unroll
    for (int off = 16; off > 0; off >>= 1) lsum += __shfl_xor_sync(0xFFFFFFFFu, lsum, off);
    if (lane == 0) s_part[warp] = lsum;
    __syncthreads();
    if (tid == 0) {
        float tot = 0.f;
#pragma unroll
        for (int w = 0; w < 8; w++) tot += s_part[w];
        tot += (float)eq_needed * funmap(T);
        float d = (tot > 0.f) ? (1.0f / sqrtf(tot)) : 0.0f;
        g_dinv[row] = d;
        g_T[row] = T;
        g_eq[row] = eq_needed;
    }
}

__global__ __launch_bounds__(RT) void k_apply(float* __restrict__ out,
                                              const float* __restrict__ mask) {
    __shared__ unsigned int s_w[8];

    int row = blockIdx.x;
    int b = row >> 11;
    int tid = threadIdx.x;
    int lane = tid & 31;
    int warp = tid >> 5;
    float minb = funmap(g_minbits[b]);
    float mk = mask[row];
    unsigned int T = g_T[row];
    unsigned int eq = g_eq[row];
    float di = g_dinv[row];
    float* rp = out + (size_t)row * NN;

    float v[EPT];
    unsigned int key[EPT];
    {
        float4 x0 = *(const float4*)(rp + tid * EPT);
        float4 x1 = *(const float4*)(rp + tid * EPT + 4);
        float xv[8] = {x0.x, x0.y, x0.z, x0.w, x1.x, x1.y, x1.z, x1.w};
#pragma unroll
        for (int q = 0; q < EPT; q++) {
            v[q] = (xv[q] - minb) * mk;
            key[q] = fmap(v[q]);
        }
    }

    unsigned int cnt = 0;
#pragma unroll
    for (int q = 0; q < EPT; q++) cnt += (key[q] == T) ? 1u : 0u;
    unsigned int incl = cnt;
#pragma unroll
    for (int off = 1; off < 32; off <<= 1) {
        unsigned int t = __shfl_up_sync(0xFFFFFFFFu, incl, off);
        if (lane >= off) incl += t;
    }
    if (lane == 31) s_w[warp] = incl;
    __syncthreads();
    unsigned int woff = 0;
#pragma unroll
    for (int w = 0; w < 8; w++)
        if (w < warp) woff += s_w[w];
    unsigned int rank = woff + incl - cnt;

    float dj[EPT];
    {
        float4 d0 = *(const float4*)(g_dinv + ((size_t)b << 11) + tid * EPT);
        float4 d1 = *(const float4*)(g_dinv + ((size_t)b << 11) + tid * EPT + 4);
        dj[0] = d0.x; dj[1] = d0.y; dj[2] = d0.z; dj[3] = d0.w;
        dj[4] = d1.x; dj[5] = d1.y; dj[6] = d1.z; dj[7] = d1.w;
    }

    float o[EPT];
#pragma unroll
    for (int q = 0; q < EPT; q++) {
        unsigned int k = key[q];
        bool keep = (k > T) || (k == T && rank < eq);
        if (k == T) rank++;
        o[q] = keep ? (di * v[q]) * dj[q] : 0.0f;
    }
    float4 y0 = make_float4(o[0], o[1], o[2], o[3]);
    float4 y1 = make_float4(o[4], o[5], o[6], o[7]);
    *(float4*)(rp + tid * EPT) = y0;
    *(float4*)(rp + tid * EPT + 4) = y1;
}

extern "C" void kernel_launch(void* const* d_in, const int* in_sizes, int n_in,
                              void* d_out, int out_size) {
    const float* ge = (const float*)d_in[0];
    const float* mask = (const float*)d_in[1];
    const float* hs = (const float*)d_in[2];
    const float* W1 = (const float*)d_in[3];
    const float* b1 = (const float*)d_in[4];
    const float* W2 = (const float*)d_in[5];
    const float* b2 = (const float*)d_in[6];
    float* out = (float*)d_out;

    cudaFuncSetAttribute(k_gemm2m, cudaFuncAttributeMaxDynamicSharedMemorySize, SMEMB);

    k_init<<<1, 32>>>();
    k_hb<<<BB, 512>>>(hs, W1, W2);
    k_gemm1<<<dim3(4, (BB * NN) / BM), 256>>>(ge, mask, W1, b1, W2, b2);
    k_gemm2m<<<dim3(NN / 128, NN / 128, BB), 256, SMEMB>>>(out);
    k_sel<<<BB * NN, RT>>>(out, mask);
    k_apply<<<BB * NN, RT>>>(out, mask);
}

// round 9
// speedup vs baseline: 1.3396x; 1.0336x over previous
#include <cuda_runtime.h>
#include <cuda_bf16.h>
#include <cstdint>

#define BB 16
#define NN 2048
#define DG 512
#define DH 512
#define OUTD 512
#define KTOP 512

// ---------------- scratch (no cudaMalloc allowed) ----------------
__device__ float g_hb1[BB * OUTD];
__device__ float g_hb2[BB * OUTD];
__device__ unsigned int g_minbits[BB];
__device__ float g_dinv[BB * NN];
__device__ unsigned int g_T[BB * NN];
__device__ unsigned int g_eq[BB * NN];
// bf16 3-way split planes of e1 (A) and e2 (B)
__device__ __nv_bfloat16 g_a0[BB * NN * OUTD];
__device__ __nv_bfloat16 g_a1[BB * NN * OUTD];
__device__ __nv_bfloat16 g_a2[BB * NN * OUTD];
__device__ __nv_bfloat16 g_b0[BB * NN * OUTD];
__device__ __nv_bfloat16 g_b1[BB * NN * OUTD];
__device__ __nv_bfloat16 g_b2[BB * NN * OUTD];

__device__ __forceinline__ unsigned int fmap(float f) {
    unsigned int u = __float_as_uint(f);
    return (u & 0x80000000u) ? ~u : (u | 0x80000000u);
}
__device__ __forceinline__ float funmap(unsigned int m) {
    unsigned int u = (m & 0x80000000u) ? (m ^ 0x80000000u) : ~m;
    return __uint_as_float(u);
}
__device__ __forceinline__ uint32_t smem_u32(const void* p) {
    uint32_t a;
    asm("{ .reg .u64 t; cvta.to.shared.u64 t, %1; cvt.u32.u64 %0, t; }" : "=r"(a) : "l"(p));
    return a;
}
__device__ __forceinline__ void ldsm4(uint32_t* r, uint32_t addr) {
    asm volatile("ldmatrix.sync.aligned.m8n8.x4.shared.b16 {%0,%1,%2,%3}, [%4];"
                 : "=r"(r[0]), "=r"(r[1]), "=r"(r[2]), "=r"(r[3]) : "r"(addr));
}
__device__ __forceinline__ void mma_bf16(float* c, const uint32_t* a, uint32_t b0, uint32_t b1) {
    asm volatile(
        "mma.sync.aligned.m16n8k16.row.col.f32.bf16.bf16.f32 "
        "{%0,%1,%2,%3}, {%4,%5,%6,%7}, {%8,%9}, {%0,%1,%2,%3};"
        : "+f"(c[0]), "+f"(c[1]), "+f"(c[2]), "+f"(c[3])
        : "r"(a[0]), "r"(a[1]), "r"(a[2]), "r"(a[3]), "r"(b0), "r"(b1));
}
__device__ __forceinline__ void cp16(uint32_t saddr, const void* g) {
    asm volatile("cp.async.cg.shared.global [%0], [%1], 16;" :: "r"(saddr), "l"(g));
}
#define CP_COMMIT() asm volatile("cp.async.commit_group;" ::: "memory")
#define CP_WAIT1() asm volatile("cp.async.wait_group 1;" ::: "memory")
#define CP_WAIT0() asm volatile("cp.async.wait_group 0;" ::: "memory")

__global__ void k_init() {
    if (threadIdx.x < BB) g_minbits[threadIdx.x] = 0xFFFFFFFFu;
}

// per-batch hidden contribution
__global__ void k_hb(const float* __restrict__ hidden,
                     const float* __restrict__ W1,
                     const float* __restrict__ W2) {
    int b = blockIdx.x;
    int o = threadIdx.x;
    const float* h = hidden + b * DH;
    float a1 = 0.f, a2 = 0.f;
#pragma unroll 4
    for (int d = 0; d < DH; d++) {
        float hv = h[d];
        a1 = fmaf(hv, W1[(size_t)(DG + d) * OUTD + o], a1);
        a2 = fmaf(hv, W2[(size_t)(DG + d) * OUTD + o], a2);
    }
    g_hb1[b * OUTD + o] = a1;
    g_hb2[b * OUTD + o] = a2;
}

#define BM 128
#define BN2 256
#define BK2 8
#define TM 16
#define TN 8

// e1/e2 GEMM (SIMT fp32, bitwise-sequential K) with fused bf16 3-way split epilogue
__global__ __launch_bounds__(256, 1) void k_gemm1(
    const float* __restrict__ ge, const float* __restrict__ mask,
    const float* __restrict__ W1, const float* __restrict__ b1,
    const float* __restrict__ W2, const float* __restrict__ b2) {
    __shared__ float As[2][BK2][BM];
    __shared__ float Bs[2][BK2][BN2];
    int bn = blockIdx.x;
    int bm = blockIdx.y;
    int tid = threadIdx.x;
    int tx = tid & 31;
    int ty = tid >> 5;
    int row0 = bm * BM;
    int col0 = (bn & 1) * BN2;

    const float* W;
    const float* bias;
    const float* hb;
    __nv_bfloat16 *P0, *P1, *P2;
    if (bn < 2) {
        W = W1; bias = b1; hb = g_hb1;
        P0 = g_a0; P1 = g_a1; P2 = g_a2;
    } else {
        W = W2; bias = b2; hb = g_hb2;
        P0 = g_b0; P1 = g_b1; P2 = g_b2;
    }

    int a_row = tid >> 1;
    int a_k4 = (tid & 1) * 4;
    int b_k = tid >> 5;
    int b_n8 = (tid & 31) * 8;

    const float* agp = ge + (size_t)(row0 + a_row) * DG + a_k4;
    const float* bgp = W + (size_t)b_k * OUTD + col0 + b_n8;

    float acc[TM][TN];
#pragma unroll
    for (int i = 0; i < TM; i++)
#pragma unroll
        for (int j = 0; j < TN; j++) acc[i][j] = 0.f;

    {
        float4 pa = *(const float4*)agp;
        float4 pb0 = *(const float4*)bgp;
        float4 pb1 = *(const float4*)(bgp + 4);
        As[0][a_k4 + 0][a_row] = pa.x;
        As[0][a_k4 + 1][a_row] = pa.y;
        As[0][a_k4 + 2][a_row] = pa.z;
        As[0][a_k4 + 3][a_row] = pa.w;
        *(float4*)&Bs[0][b_k][b_n8] = pb0;
        *(float4*)&Bs[0][b_k][b_n8 + 4] = pb1;
    }
    __syncthreads();

    for (int k0 = 0; k0 < DG; k0 += BK2) {
        int buf = (k0 >> 3) & 1;
        float4 pa, pb0, pb1;
        bool more = (k0 + BK2) < DG;
        if (more) {
            pa = *(const float4*)(agp + k0 + BK2);
            pb0 = *(const float4*)(bgp + (size_t)(k0 + BK2) * OUTD);
            pb1 = *(const float4*)(bgp + (size_t)(k0 + BK2) * OUTD + 4);
        }
#pragma unroll
        for (int kk = 0; kk < BK2; kk++) {
            float4 a0 = *(const float4*)&As[buf][kk][ty * TM];
            float4 a1v = *(const float4*)&As[buf][kk][ty * TM + 4];
            float4 a2v = *(const float4*)&As[buf][kk][ty * TM + 8];
            float4 a3v = *(const float4*)&As[buf][kk][ty * TM + 12];
            float4 bv0 = *(const float4*)&Bs[buf][kk][tx * TN];
            float4 bv1 = *(const float4*)&Bs[buf][kk][tx * TN + 4];
            float av[TM] = {a0.x, a0.y, a0.z, a0.w, a1v.x, a1v.y, a1v.z, a1v.w,
                            a2v.x, a2v.y, a2v.z, a2v.w, a3v.x, a3v.y, a3v.z, a3v.w};
            float bv[TN] = {bv0.x, bv0.y, bv0.z, bv0.w, bv1.x, bv1.y, bv1.z, bv1.w};
#pragma unroll
            for (int i = 0; i < TM; i++)
#pragma unroll
                for (int j = 0; j < TN; j++) acc[i][j] = fmaf(av[i], bv[j], acc[i][j]);
        }
        if (more) {
            int nb = buf ^ 1;
            As[nb][a_k4 + 0][a_row] = pa.x;
            As[nb][a_k4 + 1][a_row] = pa.y;
            As[nb][a_k4 + 2][a_row] = pa.z;
            As[nb][a_k4 + 3][a_row] = pa.w;
            *(float4*)&Bs[nb][b_k][b_n8] = pb0;
            *(float4*)&Bs[nb][b_k][b_n8 + 4] = pb1;
        }
        __syncthreads();
    }

    int b = row0 >> 11;
    float hbn[TN], bnn[TN];
#pragma unroll
    for (int j = 0; j < TN; j++) {
        int n = col0 + tx * TN + j;
        hbn[j] = hb[b * OUTD + n];
        bnn[j] = bias[n];
    }
#pragma unroll
    for (int i = 0; i < TM; i++) {
        int m = row0 + ty * TM + i;
        float mk = mask[m];
        size_t base = (size_t)m * OUTD + col0 + tx * TN;
        __nv_bfloat16 hh[TN], mm_[TN], ll[TN];
#pragma unroll
        for (int j = 0; j < TN; j++) {
            float o = mk * (acc[i][j] + hbn[j]) + bnn[j];
            __nv_bfloat16 h = __float2bfloat16_rn(o);
            float r = o - __bfloat162float(h);
            __nv_bfloat16 md = __float2bfloat16_rn(r);
            float r2 = r - __bfloat162float(md);
            hh[j] = h;
            mm_[j] = md;
            ll[j] = __float2bfloat16_rn(r2);
        }
        *(uint4*)(P0 + base) = *(uint4*)hh;
        *(uint4*)(P1 + base) = *(uint4*)mm_;
        *(uint4*)(P2 + base) = *(uint4*)ll;
    }
}

// ---- tensor-core gemm2 (6-term bf16 split, 2-chain magnitude-split accumulation) ----
#define KC 64
#define ST 72                      // padded row stride in bf16 elems (144B)
#define PL (128 * ST)              // elems per plane tile
#define BUFE (6 * PL)              // elems per buffer
#define SMEMB (2 * BUFE * 2)       // bytes, two buffers (221184)
#define NCHK (OUTD / KC)           // 8

__global__ __launch_bounds__(256, 1) void k_gemm2m(float* __restrict__ out) {
    extern __shared__ __nv_bfloat16 sm[];
    __shared__ unsigned int sMin;
    int tid = threadIdx.x;
    int wid = tid >> 5;
    int lane = tid & 31;
    int b = blockIdx.z;
    int row0 = blockIdx.y * 128;
    int col0 = blockIdx.x * 128;
    int wm = wid >> 2;  // 0..1
    int wn = wid & 3;   // 0..3

    if (tid == 0) sMin = 0xFFFFFFFFu;

    // loader geometry: row = tid>>1 (0..127), half = tid&1 (64B halves of 128B row)
    int lrow = tid >> 1;
    int lhalf = (tid & 1) * 32;  // bf16 elems
    size_t rbaseA = ((size_t)(b << 11) + row0 + lrow) * OUTD + lhalf;
    size_t rbaseB = ((size_t)(b << 11) + col0 + lrow) * OUTD + lhalf;
    uint32_t smb = smem_u32(sm);
    uint32_t swbase = smb + (uint32_t)(lrow * ST + lhalf) * 2;

#define LOAD_CHUNK(kk0, bufsel)                                                      \
    do {                                                                             \
        uint32_t sb_ = swbase + (uint32_t)(bufsel) * (BUFE * 2);                     \
        const __nv_bfloat16* gp_;                                                    \
        _Pragma("unroll")                                                            \
        for (int p_ = 0; p_ < 6; p_++) {                                             \
            switch (p_) {                                                            \
                case 0: gp_ = g_a0 + rbaseA; break;                                  \
                case 1: gp_ = g_a1 + rbaseA; break;                                  \
                case 2: gp_ = g_a2 + rbaseA; break;                                  \
                case 3: gp_ = g_b0 + rbaseB; break;                                  \
                case 4: gp_ = g_b1 + rbaseB; break;                                  \
                default: gp_ = g_b2 + rbaseB; break;                                 \
            }                                                                        \
            _Pragma("unroll")                                                        \
            for (int j_ = 0; j_ < 4; j_++)                                           \
                cp16(sb_ + (uint32_t)(p_ * PL + j_ * 8) * 2, gp_ + (kk0) + j_ * 8);  \
        }                                                                            \
        CP_COMMIT();                                                                 \
    } while (0)

    float shh[4][4][4], srest[4][4][4];
#pragma unroll
    for (int mf = 0; mf < 4; mf++)
#pragma unroll
        for (int nf = 0; nf < 4; nf++)
#pragma unroll
            for (int q = 0; q < 4; q++) {
                shh[mf][nf][q] = 0.f;
                srest[mf][nf][q] = 0.f;
            }

    // rest-term schedule: (a_plane, b_plane) x5 = hm, mh, hl, mm, lh
    const int pa_r[5] = {0, 1, 0, 1, 2};
    const int pb_r[5] = {1, 0, 2, 1, 0};

    LOAD_CHUNK(0, 0);

    for (int c = 0; c < NCHK; c++) {
        int buf = c & 1;
        uint32_t base = smb + buf * (BUFE * 2);
        bool more = (c + 1) < NCHK;
        if (more) {
            LOAD_CHUNK((c + 1) * KC, buf ^ 1);
            CP_WAIT1();
        } else {
            CP_WAIT0();
        }
        __syncthreads();

#pragma unroll
        for (int s = 0; s < 4; s++) {
            uint32_t afr[3][4][4];
            uint32_t bfr[3][2][4];
            {
                int arow = wm * 64 + (lane & 15);
                int acol = s * 16 + (lane >> 4) * 8;
#pragma unroll
                for (int p = 0; p < 3; p++)
#pragma unroll
                    for (int mf = 0; mf < 4; mf++)
                        ldsm4(afr[p][mf],
                              base + (uint32_t)(p * PL + (arow + mf * 16) * ST + acol) * 2);
                int nrow = wn * 32 + (lane & 7) + ((lane >> 4) & 1) * 8;
                int kcol = s * 16 + ((lane >> 3) & 1) * 8;
#pragma unroll
                for (int p = 0; p < 3; p++)
#pragma unroll
                    for (int g = 0; g < 2; g++)
                        ldsm4(bfr[p][g],
                              base + (uint32_t)((3 + p) * PL + (nrow + g * 16) * ST + kcol) * 2);
            }
#pragma unroll
            for (int mf = 0; mf < 4; mf++)
#pragma unroll
                for (int nf = 0; nf < 4; nf++) {
                    uint32_t b0 = bfr[0][nf >> 1][(nf & 1) * 2];
                    uint32_t b1 = bfr[0][nf >> 1][(nf & 1) * 2 + 1];
                    // hh term -> high-magnitude chain
                    mma_bf16(shh[mf][nf], afr[0][mf], b0, b1);
                    // 5 small terms -> rest chain
#pragma unroll
                    for (int t = 0; t < 5; t++)
                        mma_bf16(srest[mf][nf], afr[pa_r[t]][mf],
                                 bfr[pb_r[t]][nf >> 1][(nf & 1) * 2],
                                 bfr[pb_r[t]][nf >> 1][(nf & 1) * 2 + 1]);
                }
        }
        __syncthreads();
    }

    // epilogue: v = rest + hh (small-to-large, one rounding) + fused per-batch min
    float lmin = 3.402823466e+38f;
    float* outb = out + (size_t)b * NN * NN;
#pragma unroll
    for (int mf = 0; mf < 4; mf++)
#pragma unroll
        for (int nf = 0; nf < 4; nf++) {
            int r = row0 + wm * 64 + mf * 16 + (lane >> 2);
            int cc = col0 + wn * 32 + nf * 8 + (lane & 3) * 2;
            float v0x = __fadd_rn(srest[mf][nf][0], shh[mf][nf][0]);
            float v0y = __fadd_rn(srest[mf][nf][1], shh[mf][nf][1]);
            float v1x = __fadd_rn(srest[mf][nf][2], shh[mf][nf][2]);
            float v1y = __fadd_rn(srest[mf][nf][3], shh[mf][nf][3]);
            *(float2*)(outb + (size_t)r * NN + cc) = make_float2(v0x, v0y);
            *(float2*)(outb + (size_t)(r + 8) * NN + cc) = make_float2(v1x, v1y);
            lmin = fminf(lmin, fminf(fminf(v0x, v0y), fminf(v1x, v1y)));
        }
#pragma unroll
    for (int off = 16; off > 0; off >>= 1)
        lmin = fminf(lmin, __shfl_xor_sync(0xFFFFFFFFu, lmin, off));
    __syncthreads();
    if (lane == 0) atomicMin(&sMin, fmap(lmin));
    __syncthreads();
    if (tid == 0) atomicMin(&g_minbits[b], sMin);
}

// ---------------- selection / apply (unchanged) ----------------
#define RT 256
#define EPT 8
__global__ __launch_bounds__(RT) void k_sel(const float* __restrict__ out,
                                            const float* __restrict__ mask) {
    __shared__ unsigned int hist[256];
    __shared__ unsigned int warpsum[8];
    __shared__ unsigned int s_digit, s_r;
    __shared__ float s_part[8];

    int row = blockIdx.x;
    int b = row >> 11;
    int tid = threadIdx.x;
    int lane = tid & 31;
    int warp = tid >> 5;
    float minb = funmap(g_minbits[b]);
    float mk = mask[row];
    const float* rp = out + (size_t)row * NN;

    float v[EPT];
    unsigned int key[EPT];
    {
        float4 x0 = *(const float4*)(rp + tid * EPT);
        float4 x1 = *(const float4*)(rp + tid * EPT + 4);
        float xv[8] = {x0.x, x0.y, x0.z, x0.w, x1.x, x1.y, x1.z, x1.w};
#pragma unroll
        for (int q = 0; q < EPT; q++) {
            v[q] = (xv[q] - minb) * mk;
            key[q] = fmap(v[q]);
        }
    }

    unsigned int prefix = 0;
    unsigned int r = KTOP;
#pragma unroll
    for (int shift = 24; shift >= 0; shift -= 8) {
        hist[tid] = 0;
        __syncthreads();
        unsigned int pmask = (shift == 24) ? 0u : (0xFFFFFFFFu << (shift + 8));
#pragma unroll
        for (int q = 0; q < EPT; q++) {
            unsigned int k = key[q];
            bool match = ((k & pmask) == prefix);
            unsigned int d = match ? ((k >> shift) & 0xFFu) : 0xFFFFFFFFu;
            unsigned int peers = __match_any_sync(0xFFFFFFFFu, d);
            if (match && (lane == (__ffs(peers) - 1)))
                atomicAdd(&hist[d], __popc(peers));
        }
        __syncthreads();
        unsigned int h = hist[tid];
        unsigned int s = h;
#pragma unroll
        for (int off = 1; off < 32; off <<= 1) {
            unsigned int t = __shfl_down_sync(0xFFFFFFFFu, s, off);
            if (lane + off < 32) s += t;
        }
        if (lane == 0) warpsum[warp] = s;
        __syncthreads();
        unsigned int woff = 0;
#pragma unroll
        for (int w = 0; w < 8; w++)
            if (w > warp) woff += warpsum[w];
        unsigned int suffix = s + woff;
        if (suffix >= r && suffix - h < r) {
            s_digit = (unsigned int)tid;
            s_r = r - (suffix - h);
        }
        __syncthreads();
        prefix |= (s_digit << shift);
        r = s_r;
    }
    unsigned int T = prefix;
    unsigned int eq_needed = r;

    float lsum = 0.f;
#pragma unroll
    for (int q = 0; q < EPT; q++)
        if (key[q] > T) lsum += v[q];
#pragma unroll
    for (int off = 16; off > 0; off >>= 1) lsum += __shfl_xor_sync(0xFFFFFFFFu, lsum, off);
    if (lane == 0) s_part[warp] = lsum;
    __syncthreads();
    if (tid == 0) {
        float tot = 0.f;
#pragma unroll
        for (int w = 0; w < 8; w++) tot += s_part[w];
        tot += (float)eq_needed * funmap(T);
        float d = (tot > 0.f) ? (1.0f / sqrtf(tot)) : 0.0f;
        g_dinv[row] = d;
        g_T[row] = T;
        g_eq[row] = eq_needed;
    }
}

__global__ __launch_bounds__(RT) void k_apply(float* __restrict__ out,
                                              const float* __restrict__ mask) {
    __shared__ unsigned int s_w[8];

    int row = blockIdx.x;
    int b = row >> 11;
    int tid = threadIdx.x;
    int lane = tid & 31;
    int warp = tid >> 5;
    float minb = funmap(g_minbits[b]);
    float mk = mask[row];
    unsigned int T = g_T[row];
    unsigned int eq = g_eq[row];
    float di = g_dinv[row];
    float* rp = out + (size_t)row * NN;

    float v[EPT];
    unsigned int key[EPT];
    {
        float4 x0 = *(const float4*)(rp + tid * EPT);
        float4 x1 = *(const float4*)(rp + tid * EPT + 4);
        float xv[8] = {x0.x, x0.y, x0.z, x0.w, x1.x, x1.y, x1.z, x1.w};
#pragma unroll
        for (int q = 0; q < EPT; q++) {
            v[q] = (xv[q] - minb) * mk;
            key[q] = fmap(v[q]);
        }
    }

    unsigned int cnt = 0;
#pragma unroll
    for (int q = 0; q < EPT; q++) cnt += (key[q] == T) ? 1u : 0u;
    unsigned int incl = cnt;
#pragma unroll
    for (int off = 1; off < 32; off <<= 1) {
        unsigned int t = __shfl_up_sync(0xFFFFFFFFu, incl, off);
        if (lane >= off) incl += t;
    }
    if (lane == 31) s_w[warp] = incl;
    __syncthreads();
    unsigned int woff = 0;
#pragma unroll
    for (int w = 0; w < 8; w++)
        if (w < warp) woff += s_w[w];
    unsigned int rank = woff + incl - cnt;

    float dj[EPT];
    {
        float4 d0 = *(const float4*)(g_dinv + ((size_t)b << 11) + tid * EPT);
        float4 d1 = *(const float4*)(g_dinv + ((size_t)b << 11) + tid * EPT + 4);
        dj[0] = d0.x; dj[1] = d0.y; dj[2] = d0.z; dj[3] = d0.w;
        dj[4] = d1.x; dj[5] = d1.y; dj[6] = d1.z; dj[7] = d1.w;
    }

    float o[EPT];
#pragma unroll
    for (int q = 0; q < EPT; q++) {
        unsigned int k = key[q];
        bool keep = (k > T) || (k == T && rank < eq);
        if (k == T) rank++;
        o[q] = keep ? (di * v[q]) * dj[q] : 0.0f;
    }
    float4 y0 = make_float4(o[0], o[1], o[2], o[3]);
    float4 y1 = make_float4(o[4], o[5], o[6], o[7]);
    *(float4*)(rp + tid * EPT) = y0;
    *(float4*)(rp + tid * EPT + 4) = y1;
}

extern "C" void kernel_launch(void* const* d_in, const int* in_sizes, int n_in,
                              void* d_out, int out_size) {
    const float* ge = (const float*)d_in[0];
    const float* mask = (const float*)d_in[1];
    const float* hs = (const float*)d_in[2];
    const float* W1 = (const float*)d_in[3];
    const float* b1 = (const float*)d_in[4];
    const float* W2 = (const float*)d_in[5];
    const float* b2 = (const float*)d_in[6];
    float* out = (float*)d_out;

    cudaFuncSetAttribute(k_gemm2m, cudaFuncAttributeMaxDynamicSharedMemorySize, SMEMB);

    k_init<<<1, 32>>>();
    k_hb<<<BB, 512>>>(hs, W1, W2);
    k_gemm1<<<dim3(4, (BB * NN) / BM), 256>>>(ge, mask, W1, b1, W2, b2);
    k_gemm2m<<<dim3(NN / 128, NN / 128, BB), 256, SMEMB>>>(out);
    k_sel<<<BB * NN, RT>>>(out, mask);
    k_apply<<<BB * NN, RT>>>(out, mask);
}

// round 10
// speedup vs baseline: 1.3409x; 1.0009x over previous
#include <cuda_runtime.h>
#include <cuda_bf16.h>
#include <cstdint>

#define BB 16
#define NN 2048
#define DG 512
#define DH 512
#define OUTD 512
#define KTOP 512

// ---------------- scratch (no cudaMalloc allowed) ----------------
__device__ float g_hb1[BB * OUTD];
__device__ float g_hb2[BB * OUTD];
__device__ unsigned int g_minbits[BB];
__device__ float g_dinv[BB * NN];
__device__ unsigned int g_T[BB * NN];
__device__ unsigned int g_eq[BB * NN];
// bf16 3-way split planes of e1 (A) and e2 (B)
__device__ __nv_bfloat16 g_a0[BB * NN * OUTD];
__device__ __nv_bfloat16 g_a1[BB * NN * OUTD];
__device__ __nv_bfloat16 g_a2[BB * NN * OUTD];
__device__ __nv_bfloat16 g_b0[BB * NN * OUTD];
__device__ __nv_bfloat16 g_b1[BB * NN * OUTD];
__device__ __nv_bfloat16 g_b2[BB * NN * OUTD];

__device__ __forceinline__ unsigned int fmap(float f) {
    unsigned int u = __float_as_uint(f);
    return (u & 0x80000000u) ? ~u : (u | 0x80000000u);
}
__device__ __forceinline__ float funmap(unsigned int m) {
    unsigned int u = (m & 0x80000000u) ? (m ^ 0x80000000u) : ~m;
    return __uint_as_float(u);
}
__device__ __forceinline__ uint32_t smem_u32(const void* p) {
    uint32_t a;
    asm("{ .reg .u64 t; cvta.to.shared.u64 t, %1; cvt.u32.u64 %0, t; }" : "=r"(a) : "l"(p));
    return a;
}
__device__ __forceinline__ void ldsm4(uint32_t* r, uint32_t addr) {
    asm volatile("ldmatrix.sync.aligned.m8n8.x4.shared.b16 {%0,%1,%2,%3}, [%4];"
                 : "=r"(r[0]), "=r"(r[1]), "=r"(r[2]), "=r"(r[3]) : "r"(addr));
}
__device__ __forceinline__ void mma_bf16(float* c, const uint32_t* a, uint32_t b0, uint32_t b1) {
    asm volatile(
        "mma.sync.aligned.m16n8k16.row.col.f32.bf16.bf16.f32 "
        "{%0,%1,%2,%3}, {%4,%5,%6,%7}, {%8,%9}, {%0,%1,%2,%3};"
        : "+f"(c[0]), "+f"(c[1]), "+f"(c[2]), "+f"(c[3])
        : "r"(a[0]), "r"(a[1]), "r"(a[2]), "r"(a[3]), "r"(b0), "r"(b1));
}
__device__ __forceinline__ void cp16(uint32_t saddr, const void* g) {
    asm volatile("cp.async.cg.shared.global [%0], [%1], 16;" :: "r"(saddr), "l"(g));
}
#define CP_COMMIT() asm volatile("cp.async.commit_group;" ::: "memory")
#define CP_WAIT1() asm volatile("cp.async.wait_group 1;" ::: "memory")
#define CP_WAIT0() asm volatile("cp.async.wait_group 0;" ::: "memory")

__global__ void k_init() {
    if (threadIdx.x < BB) g_minbits[threadIdx.x] = 0xFFFFFFFFu;
}

// per-batch hidden contribution
__global__ void k_hb(const float* __restrict__ hidden,
                     const float* __restrict__ W1,
                     const float* __restrict__ W2) {
    int b = blockIdx.x;
    int o = threadIdx.x;
    const float* h = hidden + b * DH;
    float a1 = 0.f, a2 = 0.f;
#pragma unroll 4
    for (int d = 0; d < DH; d++) {
        float hv = h[d];
        a1 = fmaf(hv, W1[(size_t)(DG + d) * OUTD + o], a1);
        a2 = fmaf(hv, W2[(size_t)(DG + d) * OUTD + o], a2);
    }
    g_hb1[b * OUTD + o] = a1;
    g_hb2[b * OUTD + o] = a2;
}

#define BM 128
#define BN2 256
#define BK2 8
#define TM 16
#define TN 8

// e1/e2 GEMM (SIMT fp32, bitwise-sequential K) with fused bf16 3-way split epilogue
__global__ __launch_bounds__(256, 1) void k_gemm1(
    const float* __restrict__ ge, const float* __restrict__ mask,
    const float* __restrict__ W1, const float* __restrict__ b1,
    const float* __restrict__ W2, const float* __restrict__ b2) {
    __shared__ float As[2][BK2][BM];
    __shared__ float Bs[2][BK2][BN2];
    int bn = blockIdx.x;
    int bm = blockIdx.y;
    int tid = threadIdx.x;
    int tx = tid & 31;
    int ty = tid >> 5;
    int row0 = bm * BM;
    int col0 = (bn & 1) * BN2;

    const float* W;
    const float* bias;
    const float* hb;
    __nv_bfloat16 *P0, *P1, *P2;
    if (bn < 2) {
        W = W1; bias = b1; hb = g_hb1;
        P0 = g_a0; P1 = g_a1; P2 = g_a2;
    } else {
        W = W2; bias = b2; hb = g_hb2;
        P0 = g_b0; P1 = g_b1; P2 = g_b2;
    }

    int a_row = tid >> 1;
    int a_k4 = (tid & 1) * 4;
    int b_k = tid >> 5;
    int b_n8 = (tid & 31) * 8;

    const float* agp = ge + (size_t)(row0 + a_row) * DG + a_k4;
    const float* bgp = W + (size_t)b_k * OUTD + col0 + b_n8;

    float acc[TM][TN];
#pragma unroll
    for (int i = 0; i < TM; i++)
#pragma unroll
        for (int j = 0; j < TN; j++) acc[i][j] = 0.f;

    {
        float4 pa = *(const float4*)agp;
        float4 pb0 = *(const float4*)bgp;
        float4 pb1 = *(const float4*)(bgp + 4);
        As[0][a_k4 + 0][a_row] = pa.x;
        As[0][a_k4 + 1][a_row] = pa.y;
        As[0][a_k4 + 2][a_row] = pa.z;
        As[0][a_k4 + 3][a_row] = pa.w;
        *(float4*)&Bs[0][b_k][b_n8] = pb0;
        *(float4*)&Bs[0][b_k][b_n8 + 4] = pb1;
    }
    __syncthreads();

    for (int k0 = 0; k0 < DG; k0 += BK2) {
        int buf = (k0 >> 3) & 1;
        float4 pa, pb0, pb1;
        bool more = (k0 + BK2) < DG;
        if (more) {
            pa = *(const float4*)(agp + k0 + BK2);
            pb0 = *(const float4*)(bgp + (size_t)(k0 + BK2) * OUTD);
            pb1 = *(const float4*)(bgp + (size_t)(k0 + BK2) * OUTD + 4);
        }
#pragma unroll
        for (int kk = 0; kk < BK2; kk++) {
            float4 a0 = *(const float4*)&As[buf][kk][ty * TM];
            float4 a1v = *(const float4*)&As[buf][kk][ty * TM + 4];
            float4 a2v = *(const float4*)&As[buf][kk][ty * TM + 8];
            float4 a3v = *(const float4*)&As[buf][kk][ty * TM + 12];
            float4 bv0 = *(const float4*)&Bs[buf][kk][tx * TN];
            float4 bv1 = *(const float4*)&Bs[buf][kk][tx * TN + 4];
            float av[TM] = {a0.x, a0.y, a0.z, a0.w, a1v.x, a1v.y, a1v.z, a1v.w,
                            a2v.x, a2v.y, a2v.z, a2v.w, a3v.x, a3v.y, a3v.z, a3v.w};
            float bv[TN] = {bv0.x, bv0.y, bv0.z, bv0.w, bv1.x, bv1.y, bv1.z, bv1.w};
#pragma unroll
            for (int i = 0; i < TM; i++)
#pragma unroll
                for (int j = 0; j < TN; j++) acc[i][j] = fmaf(av[i], bv[j], acc[i][j]);
        }
        if (more) {
            int nb = buf ^ 1;
            As[nb][a_k4 + 0][a_row] = pa.x;
            As[nb][a_k4 + 1][a_row] = pa.y;
            As[nb][a_k4 + 2][a_row] = pa.z;
            As[nb][a_k4 + 3][a_row] = pa.w;
            *(float4*)&Bs[nb][b_k][b_n8] = pb0;
            *(float4*)&Bs[nb][b_k][b_n8 + 4] = pb1;
        }
        __syncthreads();
    }

    int b = row0 >> 11;
    float hbn[TN], bnn[TN];
#pragma unroll
    for (int j = 0; j < TN; j++) {
        int n = col0 + tx * TN + j;
        hbn[j] = hb[b * OUTD + n];
        bnn[j] = bias[n];
    }
#pragma unroll
    for (int i = 0; i < TM; i++) {
        int m = row0 + ty * TM + i;
        float mk = mask[m];
        size_t base = (size_t)m * OUTD + col0 + tx * TN;
        __nv_bfloat16 hh[TN], mm_[TN], ll[TN];
#pragma unroll
        for (int j = 0; j < TN; j++) {
            float o = mk * (acc[i][j] + hbn[j]) + bnn[j];
            __nv_bfloat16 h = __float2bfloat16_rn(o);
            float r = o - __bfloat162float(h);
            __nv_bfloat16 md = __float2bfloat16_rn(r);
            float r2 = r - __bfloat162float(md);
            hh[j] = h;
            mm_[j] = md;
            ll[j] = __float2bfloat16_rn(r2);
        }
        *(uint4*)(P0 + base) = *(uint4*)hh;
        *(uint4*)(P1 + base) = *(uint4*)mm_;
        *(uint4*)(P2 + base) = *(uint4*)ll;
    }
}

// ---- tensor-core gemm2 (6-term bf16 split, 2-chain magnitude-split accumulation) ----
#define KC 64
#define ST 72                      // padded row stride in bf16 elems (144B)
#define PL (128 * ST)              // elems per plane tile
#define BUFE (6 * PL)              // elems per buffer
#define SMEMB (2 * BUFE * 2)       // bytes, two buffers (221184)
#define NCHK (OUTD / KC)           // 8

__global__ __launch_bounds__(256, 1) void k_gemm2m(float* __restrict__ out) {
    extern __shared__ __nv_bfloat16 sm[];
    __shared__ unsigned int sMin;
    int tid = threadIdx.x;
    int wid = tid >> 5;
    int lane = tid & 31;
    int b = blockIdx.z;
    int row0 = blockIdx.y * 128;
    int col0 = blockIdx.x * 128;
    int wm = wid >> 2;  // 0..1
    int wn = wid & 3;   // 0..3

    if (tid == 0) sMin = 0xFFFFFFFFu;

    // loader geometry: row = tid>>1 (0..127), half = tid&1 (64B halves of 128B row)
    int lrow = tid >> 1;
    int lhalf = (tid & 1) * 32;  // bf16 elems
    size_t rbaseA = ((size_t)(b << 11) + row0 + lrow) * OUTD + lhalf;
    size_t rbaseB = ((size_t)(b << 11) + col0 + lrow) * OUTD + lhalf;
    uint32_t smb = smem_u32(sm);
    uint32_t swbase = smb + (uint32_t)(lrow * ST + lhalf) * 2;

#define LOAD_CHUNK(kk0, bufsel)                                                      \
    do {                                                                             \
        uint32_t sb_ = swbase + (uint32_t)(bufsel) * (BUFE * 2);                     \
        const __nv_bfloat16* gp_;                                                    \
        _Pragma("unroll")                                                            \
        for (int p_ = 0; p_ < 6; p_++) {                                             \
            switch (p_) {                                                            \
                case 0: gp_ = g_a0 + rbaseA; break;                                  \
                case 1: gp_ = g_a1 + rbaseA; break;                                  \
                case 2: gp_ = g_a2 + rbaseA; break;                                  \
                case 3: gp_ = g_b0 + rbaseB; break;                                  \
                case 4: gp_ = g_b1 + rbaseB; break;                                  \
                default: gp_ = g_b2 + rbaseB; break;                                 \
            }                                                                        \
            _Pragma("unroll")                                                        \
            for (int j_ = 0; j_ < 4; j_++)                                           \
                cp16(sb_ + (uint32_t)(p_ * PL + j_ * 8) * 2, gp_ + (kk0) + j_ * 8);  \
        }                                                                            \
        CP_COMMIT();                                                                 \
    } while (0)

    float shh[4][4][4], srest[4][4][4];
#pragma unroll
    for (int mf = 0; mf < 4; mf++)
#pragma unroll
        for (int nf = 0; nf < 4; nf++)
#pragma unroll
            for (int q = 0; q < 4; q++) {
                shh[mf][nf][q] = 0.f;
                srest[mf][nf][q] = 0.f;
            }

    LOAD_CHUNK(0, 0);

    for (int c = 0; c < NCHK; c++) {
        int buf = c & 1;
        uint32_t base = smb + buf * (BUFE * 2);
        bool more = (c + 1) < NCHK;
        if (more) {
            LOAD_CHUNK((c + 1) * KC, buf ^ 1);
            CP_WAIT1();
        } else {
            CP_WAIT0();
        }
        __syncthreads();

#pragma unroll
        for (int s = 0; s < 4; s++) {
            uint32_t afr[3][4][4];
            uint32_t bfr[3][2][4];
            {
                int arow = wm * 64 + (lane & 15);
                int acol = s * 16 + (lane >> 4) * 8;
#pragma unroll
                for (int p = 0; p < 3; p++)
#pragma unroll
                    for (int mf = 0; mf < 4; mf++)
                        ldsm4(afr[p][mf],
                              base + (uint32_t)(p * PL + (arow + mf * 16) * ST + acol) * 2);
                int nrow = wn * 32 + (lane & 7) + ((lane >> 4) & 1) * 8;
                int kcol = s * 16 + ((lane >> 3) & 1) * 8;
#pragma unroll
                for (int p = 0; p < 3; p++)
#pragma unroll
                    for (int g = 0; g < 2; g++)
                        ldsm4(bfr[p][g],
                              base + (uint32_t)((3 + p) * PL + (nrow + g * 16) * ST + kcol) * 2);
            }
            // term-outer schedule: 16 independent MMAs back-to-back per term.
            // Per-accumulator order is unchanged vs round 9 (numerics bitwise identical).
            // t=0: hh -> shh; t=1..5: hm, mh, hl, mm, lh -> srest
            const int pa_t[6] = {0, 0, 1, 0, 1, 2};
            const int pb_t[6] = {0, 1, 0, 2, 1, 0};
#pragma unroll
            for (int t = 0; t < 6; t++) {
                int pa = pa_t[t], pb = pb_t[t];
                float (*dst)[4][4] = (t == 0) ? shh : srest;
#pragma unroll
                for (int mf = 0; mf < 4; mf++)
#pragma unroll
                    for (int nf = 0; nf < 4; nf++)
                        mma_bf16(dst[mf][nf], afr[pa][mf],
                                 bfr[pb][nf >> 1][(nf & 1) * 2],
                                 bfr[pb][nf >> 1][(nf & 1) * 2 + 1]);
            }
        }
        __syncthreads();
    }

    // epilogue: v = rest + hh (small-to-large, one rounding) + fused per-batch min
    float lmin = 3.402823466e+38f;
    float* outb = out + (size_t)b * NN * NN;
#pragma unroll
    for (int mf = 0; mf < 4; mf++)
#pragma unroll
        for (int nf = 0; nf < 4; nf++) {
            int r = row0 + wm * 64 + mf * 16 + (lane >> 2);
            int cc = col0 + wn * 32 + nf * 8 + (lane & 3) * 2;
            float v0x = __fadd_rn(srest[mf][nf][0], shh[mf][nf][0]);
            float v0y = __fadd_rn(srest[mf][nf][1], shh[mf][nf][1]);
            float v1x = __fadd_rn(srest[mf][nf][2], shh[mf][nf][2]);
            float v1y = __fadd_rn(srest[mf][nf][3], shh[mf][nf][3]);
            *(float2*)(outb + (size_t)r * NN + cc) = make_float2(v0x, v0y);
            *(float2*)(outb + (size_t)(r + 8) * NN + cc) = make_float2(v1x, v1y);
            lmin = fminf(lmin, fminf(fminf(v0x, v0y), fminf(v1x, v1y)));
        }
#pragma unroll
    for (int off = 16; off > 0; off >>= 1)
        lmin = fminf(lmin, __shfl_xor_sync(0xFFFFFFFFu, lmin, off));
    __syncthreads();
    if (lane == 0) atomicMin(&sMin, fmap(lmin));
    __syncthreads();
    if (tid == 0) atomicMin(&g_minbits[b], sMin);
}

// ---------------- selection / apply (unchanged) ----------------
#define RT 256
#define EPT 8
__global__ __launch_bounds__(RT) void k_sel(const float* __restrict__ out,
                                            const float* __restrict__ mask) {
    __shared__ unsigned int hist[256];
    __shared__ unsigned int warpsum[8];
    __shared__ unsigned int s_digit, s_r;
    __shared__ float s_part[8];

    int row = blockIdx.x;
    int b = row >> 11;
    int tid = threadIdx.x;
    int lane = tid & 31;
    int warp = tid >> 5;
    float minb = funmap(g_minbits[b]);
    float mk = mask[row];
    const float* rp = out + (size_t)row * NN;

    float v[EPT];
    unsigned int key[EPT];
    {
        float4 x0 = *(const float4*)(rp + tid * EPT);
        float4 x1 = *(const float4*)(rp + tid * EPT + 4);
        float xv[8] = {x0.x, x0.y, x0.z, x0.w, x1.x, x1.y, x1.z, x1.w};
#pragma unroll
        for (int q = 0; q < EPT; q++) {
            v[q] = (xv[q] - minb) * mk;
            key[q] = fmap(v[q]);
        }
    }

    unsigned int prefix = 0;
    unsigned int r = KTOP;
#pragma unroll
    for (int shift = 24; shift >= 0; shift -= 8) {
        hist[tid] = 0;
        __syncthreads();
        unsigned int pmask = (shift == 24) ? 0u : (0xFFFFFFFFu << (shift + 8));
#pragma unroll
        for (int q = 0; q < EPT; q++) {
            unsigned int k = key[q];
            bool match = ((k & pmask) == prefix);
            unsigned int d = match ? ((k >> shift) & 0xFFu) : 0xFFFFFFFFu;
            unsigned int peers = __match_any_sync(0xFFFFFFFFu, d);
            if (match && (lane == (__ffs(peers) - 1)))
                atomicAdd(&hist[d], __popc(peers));
        }
        __syncthreads();
        unsigned int h = hist[tid];
        unsigned int s = h;
#pragma unroll
        for (int off = 1; off < 32; off <<= 1) {
            unsigned int t = __shfl_down_sync(0xFFFFFFFFu, s, off);
            if (lane + off < 32) s += t;
        }
        if (lane == 0) warpsum[warp] = s;
        __syncthreads();
        unsigned int woff = 0;
#pragma unroll
        for (int w = 0; w < 8; w++)
            if (w > warp) woff += warpsum[w];
        unsigned int suffix = s + woff;
        if (suffix >= r && suffix - h < r) {
            s_digit = (unsigned int)tid;
            s_r = r - (suffix - h);
        }
        __syncthreads();
        prefix |= (s_digit << shift);
        r = s_r;
    }
    unsigned int T = prefix;
    unsigned int eq_needed = r;

    float lsum = 0.f;
#pragma unroll
    for (int q = 0; q < EPT; q++)
        if (key[q] > T) lsum += v[q];
#pragma unroll
    for (int off = 16; off > 0; off >>= 1) lsum += __shfl_xor_sync(0xFFFFFFFFu, lsum, off);
    if (lane == 0) s_part[warp] = lsum;
    __syncthreads();
    if (tid == 0) {
        float tot = 0.f;
#pragma unroll
        for (int w = 0; w < 8; w++) tot += s_part[w];
        tot += (float)eq_needed * funmap(T);
        float d = (tot > 0.f) ? (1.0f / sqrtf(tot)) : 0.0f;
        g_dinv[row] = d;
        g_T[row] = T;
        g_eq[row] = eq_needed;
    }
}

__global__ __launch_bounds__(RT) void k_apply(float* __restrict__ out,
                                              const float* __restrict__ mask) {
    __shared__ unsigned int s_w[8];

    int row = blockIdx.x;
    int b = row >> 11;
    int tid = threadIdx.x;
    int lane = tid & 31;
    int warp = tid >> 5;
    float minb = funmap(g_minbits[b]);
    float mk = mask[row];
    unsigned int T = g_T[row];
    unsigned int eq = g_eq[row];
    float di = g_dinv[row];
    float* rp = out + (size_t)row * NN;

    float v[EPT];
    unsigned int key[EPT];
    {
        float4 x0 = *(const float4*)(rp + tid * EPT);
        float4 x1 = *(const float4*)(rp + tid * EPT + 4);
        float xv[8] = {x0.x, x0.y, x0.z, x0.w, x1.x, x1.y, x1.z, x1.w};
#pragma unroll
        for (int q = 0; q < EPT; q++) {
            v[q] = (xv[q] - minb) * mk;
            key[q] = fmap(v[q]);
        }
    }

    unsigned int cnt = 0;
#pragma unroll
    for (int q = 0; q < EPT; q++) cnt += (key[q] == T) ? 1u : 0u;
    unsigned int incl = cnt;
#pragma unroll
    for (int off = 1; off < 32; off <<= 1) {
        unsigned int t = __shfl_up_sync(0xFFFFFFFFu, incl, off);
        if (lane >= off) incl += t;
    }
    if (lane == 31) s_w[warp] = incl;
    __syncthreads();
    unsigned int woff = 0;
#pragma unroll
    for (int w = 0; w < 8; w++)
        if (w < warp) woff += s_w[w];
    unsigned int rank = woff + incl - cnt;

    float dj[EPT];
    {
        float4 d0 = *(const float4*)(g_dinv + ((size_t)b << 11) + tid * EPT);
        float4 d1 = *(const float4*)(g_dinv + ((size_t)b << 11) + tid * EPT + 4);
        dj[0] = d0.x; dj[1] = d0.y; dj[2] = d0.z; dj[3] = d0.w;
        dj[4] = d1.x; dj[5] = d1.y; dj[6] = d1.z; dj[7] = d1.w;
    }

    float o[EPT];
#pragma unroll
    for (int q = 0; q < EPT; q++) {
        unsigned int k = key[q];
        bool keep = (k > T) || (k == T && rank < eq);
        if (k == T) rank++;
        o[q] = keep ? (di * v[q]) * dj[q] : 0.0f;
    }
    float4 y0 = make_float4(o[0], o[1], o[2], o[3]);
    float4 y1 = make_float4(o[4], o[5], o[6], o[7]);
    *(float4*)(rp + tid * EPT) = y0;
    *(float4*)(rp + tid * EPT + 4) = y1;
}

extern "C" void kernel_launch(void* const* d_in, const int* in_sizes, int n_in,
                              void* d_out, int out_size) {
    const float* ge = (const float*)d_in[0];
    const float* mask = (const float*)d_in[1];
    const float* hs = (const float*)d_in[2];
    const float* W1 = (const float*)d_in[3];
    const float* b1 = (const float*)d_in[4];
    const float* W2 = (const float*)d_in[5];
    const float* b2 = (const float*)d_in[6];
    float* out = (float*)d_out;

    cudaFuncSetAttribute(k_gemm2m, cudaFuncAttributeMaxDynamicSharedMemorySize, SMEMB);

    k_init<<<1, 32>>>();
    k_hb<<<BB, 512>>>(hs, W1, W2);
    k_gemm1<<<dim3(4, (BB * NN) / BM), 256>>>(ge, mask, W1, b1, W2, b2);
    k_gemm2m<<<dim3(NN / 128, NN / 128, BB), 256, SMEMB>>>(out);
    k_sel<<<BB * NN, RT>>>(out, mask);
    k_apply<<<BB * NN, RT>>>(out, mask);
}

// round 11
// speedup vs baseline: 1.4535x; 1.0840x over previous
#include <cuda_runtime.h>
#include <cuda_bf16.h>
#include <cstdint>

#define BB 16
#define NN 2048
#define DG 512
#define DH 512
#define OUTD 512
#define KTOP 512

// ---------------- scratch (no cudaMalloc allowed) ----------------
__device__ float g_hb1[BB * OUTD];
__device__ float g_hb2[BB * OUTD];
__device__ unsigned int g_minbits[BB];
__device__ float g_dinv[BB * NN];
__device__ unsigned int g_T[BB * NN];
__device__ unsigned int g_eq[BB * NN];
// bf16 3-way split planes of e1 (A) and e2 (B)
__device__ __nv_bfloat16 g_a0[BB * NN * OUTD];
__device__ __nv_bfloat16 g_a1[BB * NN * OUTD];
__device__ __nv_bfloat16 g_a2[BB * NN * OUTD];
__device__ __nv_bfloat16 g_b0[BB * NN * OUTD];
__device__ __nv_bfloat16 g_b1[BB * NN * OUTD];
__device__ __nv_bfloat16 g_b2[BB * NN * OUTD];

__device__ __forceinline__ unsigned int fmap(float f) {
    unsigned int u = __float_as_uint(f);
    return (u & 0x80000000u) ? ~u : (u | 0x80000000u);
}
__device__ __forceinline__ float funmap(unsigned int m) {
    unsigned int u = (m & 0x80000000u) ? (m ^ 0x80000000u) : ~m;
    return __uint_as_float(u);
}
__device__ __forceinline__ uint32_t smem_u32(const void* p) {
    uint32_t a;
    asm("{ .reg .u64 t; cvta.to.shared.u64 t, %1; cvt.u32.u64 %0, t; }" : "=r"(a) : "l"(p));
    return a;
}
__device__ __forceinline__ void ldsm4(uint32_t* r, uint32_t addr) {
    asm volatile("ldmatrix.sync.aligned.m8n8.x4.shared.b16 {%0,%1,%2,%3}, [%4];"
                 : "=r"(r[0]), "=r"(r[1]), "=r"(r[2]), "=r"(r[3]) : "r"(addr));
}
__device__ __forceinline__ void mma_bf16(float* c, const uint32_t* a, uint32_t b0, uint32_t b1) {
    asm volatile(
        "mma.sync.aligned.m16n8k16.row.col.f32.bf16.bf16.f32 "
        "{%0,%1,%2,%3}, {%4,%5,%6,%7}, {%8,%9}, {%0,%1,%2,%3};"
        : "+f"(c[0]), "+f"(c[1]), "+f"(c[2]), "+f"(c[3])
        : "r"(a[0]), "r"(a[1]), "r"(a[2]), "r"(a[3]), "r"(b0), "r"(b1));
}
__device__ __forceinline__ void cp16(uint32_t saddr, const void* g) {
    asm volatile("cp.async.cg.shared.global [%0], [%1], 16;" :: "r"(saddr), "l"(g));
}
#define CP_COMMIT() asm volatile("cp.async.commit_group;" ::: "memory")
#define CP_WAIT1() asm volatile("cp.async.wait_group 1;" ::: "memory")
#define CP_WAIT0() asm volatile("cp.async.wait_group 0;" ::: "memory")

__global__ void k_init() {
    if (threadIdx.x < BB) g_minbits[threadIdx.x] = 0xFFFFFFFFu;
}

// per-batch hidden contribution
__global__ void k_hb(const float* __restrict__ hidden,
                     const float* __restrict__ W1,
                     const float* __restrict__ W2) {
    int b = blockIdx.x;
    int o = threadIdx.x;
    const float* h = hidden + b * DH;
    float a1 = 0.f, a2 = 0.f;
#pragma unroll 4
    for (int d = 0; d < DH; d++) {
        float hv = h[d];
        a1 = fmaf(hv, W1[(size_t)(DG + d) * OUTD + o], a1);
        a2 = fmaf(hv, W2[(size_t)(DG + d) * OUTD + o], a2);
    }
    g_hb1[b * OUTD + o] = a1;
    g_hb2[b * OUTD + o] = a2;
}

#define BM 128
#define BN2 256
#define BK2 8
#define TM 16
#define TN 8

// e1/e2 GEMM (SIMT fp32, bitwise-sequential K) with fused bf16 3-way split epilogue
__global__ __launch_bounds__(256, 1) void k_gemm1(
    const float* __restrict__ ge, const float* __restrict__ mask,
    const float* __restrict__ W1, const float* __restrict__ b1,
    const float* __restrict__ W2, const float* __restrict__ b2) {
    __shared__ float As[2][BK2][BM];
    __shared__ float Bs[2][BK2][BN2];
    int bn = blockIdx.x;
    int bm = blockIdx.y;
    int tid = threadIdx.x;
    int tx = tid & 31;
    int ty = tid >> 5;
    int row0 = bm * BM;
    int col0 = (bn & 1) * BN2;

    const float* W;
    const float* bias;
    const float* hb;
    __nv_bfloat16 *P0, *P1, *P2;
    if (bn < 2) {
        W = W1; bias = b1; hb = g_hb1;
        P0 = g_a0; P1 = g_a1; P2 = g_a2;
    } else {
        W = W2; bias = b2; hb = g_hb2;
        P0 = g_b0; P1 = g_b1; P2 = g_b2;
    }

    int a_row = tid >> 1;
    int a_k4 = (tid & 1) * 4;
    int b_k = tid >> 5;
    int b_n8 = (tid & 31) * 8;

    const float* agp = ge + (size_t)(row0 + a_row) * DG + a_k4;
    const float* bgp = W + (size_t)b_k * OUTD + col0 + b_n8;

    float acc[TM][TN];
#pragma unroll
    for (int i = 0; i < TM; i++)
#pragma unroll
        for (int j = 0; j < TN; j++) acc[i][j] = 0.f;

    {
        float4 pa = *(const float4*)agp;
        float4 pb0 = *(const float4*)bgp;
        float4 pb1 = *(const float4*)(bgp + 4);
        As[0][a_k4 + 0][a_row] = pa.x;
        As[0][a_k4 + 1][a_row] = pa.y;
        As[0][a_k4 + 2][a_row] = pa.z;
        As[0][a_k4 + 3][a_row] = pa.w;
        *(float4*)&Bs[0][b_k][b_n8] = pb0;
        *(float4*)&Bs[0][b_k][b_n8 + 4] = pb1;
    }
    __syncthreads();

    for (int k0 = 0; k0 < DG; k0 += BK2) {
        int buf = (k0 >> 3) & 1;
        float4 pa, pb0, pb1;
        bool more = (k0 + BK2) < DG;
        if (more) {
            pa = *(const float4*)(agp + k0 + BK2);
            pb0 = *(const float4*)(bgp + (size_t)(k0 + BK2) * OUTD);
            pb1 = *(const float4*)(bgp + (size_t)(k0 + BK2) * OUTD + 4);
        }
#pragma unroll
        for (int kk = 0; kk < BK2; kk++) {
            float4 a0 = *(const float4*)&As[buf][kk][ty * TM];
            float4 a1v = *(const float4*)&As[buf][kk][ty * TM + 4];
            float4 a2v = *(const float4*)&As[buf][kk][ty * TM + 8];
            float4 a3v = *(const float4*)&As[buf][kk][ty * TM + 12];
            float4 bv0 = *(const float4*)&Bs[buf][kk][tx * TN];
            float4 bv1 = *(const float4*)&Bs[buf][kk][tx * TN + 4];
            float av[TM] = {a0.x, a0.y, a0.z, a0.w, a1v.x, a1v.y, a1v.z, a1v.w,
                            a2v.x, a2v.y, a2v.z, a2v.w, a3v.x, a3v.y, a3v.z, a3v.w};
            float bv[TN] = {bv0.x, bv0.y, bv0.z, bv0.w, bv1.x, bv1.y, bv1.z, bv1.w};
#pragma unroll
            for (int i = 0; i < TM; i++)
#pragma unroll
                for (int j = 0; j < TN; j++) acc[i][j] = fmaf(av[i], bv[j], acc[i][j]);
        }
        if (more) {
            int nb = buf ^ 1;
            As[nb][a_k4 + 0][a_row] = pa.x;
            As[nb][a_k4 + 1][a_row] = pa.y;
            As[nb][a_k4 + 2][a_row] = pa.z;
            As[nb][a_k4 + 3][a_row] = pa.w;
            *(float4*)&Bs[nb][b_k][b_n8] = pb0;
            *(float4*)&Bs[nb][b_k][b_n8 + 4] = pb1;
        }
        __syncthreads();
    }

    int b = row0 >> 11;
    float hbn[TN], bnn[TN];
#pragma unroll
    for (int j = 0; j < TN; j++) {
        int n = col0 + tx * TN + j;
        hbn[j] = hb[b * OUTD + n];
        bnn[j] = bias[n];
    }
#pragma unroll
    for (int i = 0; i < TM; i++) {
        int m = row0 + ty * TM + i;
        float mk = mask[m];
        size_t base = (size_t)m * OUTD + col0 + tx * TN;
        __nv_bfloat16 hh[TN], mm_[TN], ll[TN];
#pragma unroll
        for (int j = 0; j < TN; j++) {
            float o = mk * (acc[i][j] + hbn[j]) + bnn[j];
            __nv_bfloat16 h = __float2bfloat16_rn(o);
            float r = o - __bfloat162float(h);
            __nv_bfloat16 md = __float2bfloat16_rn(r);
            float r2 = r - __bfloat162float(md);
            hh[j] = h;
            mm_[j] = md;
            ll[j] = __float2bfloat16_rn(r2);
        }
        *(uint4*)(P0 + base) = *(uint4*)hh;
        *(uint4*)(P1 + base) = *(uint4*)mm_;
        *(uint4*)(P2 + base) = *(uint4*)ll;
    }
}

// ---- tensor-core gemm2 v2: 128x64 CTA tile, 32x32 warp tiles, 2 CTAs/SM ----
#define KC2 32
#define ST2 40                      // padded row stride in bf16 elems (80B)
#define PLA (128 * ST2)             // A plane elems (5120)
#define PLB (64 * ST2)              // B plane elems (2560)
#define BUFE2 (3 * PLA + 3 * PLB)   // elems per buffer (23040)
#define SMEMB2 (2 * BUFE2 * 2)      // 92160 bytes
#define NCHK2 (OUTD / KC2)          // 16

__global__ __launch_bounds__(256, 2) void k_gemm2m(float* __restrict__ out) {
    extern __shared__ __nv_bfloat16 sm[];
    __shared__ unsigned int sMin;
    int tid = threadIdx.x;
    int wid = tid >> 5;
    int lane = tid & 31;
    int b = blockIdx.z;
    int row0 = blockIdx.y * 128;
    int col0 = blockIdx.x * 64;
    int wm = wid >> 1;  // 0..3 (32-row slices)
    int wn = wid & 1;   // 0..1 (32-col slices)

    if (tid == 0) sMin = 0xFFFFFFFFu;

    // loader geometry: 4 threads per row (16B each covering 64B = 32 bf16)
    int lrow = tid >> 2;       // 0..63
    int lg = (tid & 3) * 8;    // bf16 elem offset
    size_t rA0 = ((size_t)(b << 11) + row0 + lrow) * OUTD + lg;
    size_t rA1 = rA0 + (size_t)64 * OUTD;
    size_t rB = ((size_t)(b << 11) + col0 + lrow) * OUTD + lg;
    uint32_t smb = smem_u32(sm);
    uint32_t sA0 = smb + (uint32_t)(lrow * ST2 + lg) * 2;
    uint32_t sA1 = sA0 + 64 * ST2 * 2;
    uint32_t sB = smb + (uint32_t)(3 * PLA + lrow * ST2 + lg) * 2;

#define LOAD_CHUNK2(kk0, bufsel)                                        \
    do {                                                                \
        uint32_t bo_ = (uint32_t)(bufsel) * (BUFE2 * 2);                \
        cp16(sA0 + bo_ + 0 * (PLA * 2), g_a0 + rA0 + (kk0));            \
        cp16(sA1 + bo_ + 0 * (PLA * 2), g_a0 + rA1 + (kk0));            \
        cp16(sA0 + bo_ + 1 * (PLA * 2), g_a1 + rA0 + (kk0));            \
        cp16(sA1 + bo_ + 1 * (PLA * 2), g_a1 + rA1 + (kk0));            \
        cp16(sA0 + bo_ + 2 * (PLA * 2), g_a2 + rA0 + (kk0));            \
        cp16(sA1 + bo_ + 2 * (PLA * 2), g_a2 + rA1 + (kk0));            \
        cp16(sB + bo_ + 0 * (PLB * 2), g_b0 + rB + (kk0));              \
        cp16(sB + bo_ + 1 * (PLB * 2), g_b1 + rB + (kk0));              \
        cp16(sB + bo_ + 2 * (PLB * 2), g_b2 + rB + (kk0));              \
        CP_COMMIT();                                                    \
    } while (0)

    float shh[2][4][4], srest[2][4][4];
#pragma unroll
    for (int mf = 0; mf < 2; mf++)
#pragma unroll
        for (int nf = 0; nf < 4; nf++)
#pragma unroll
            for (int q = 0; q < 4; q++) {
                shh[mf][nf][q] = 0.f;
                srest[mf][nf][q] = 0.f;
            }

    LOAD_CHUNK2(0, 0);

    for (int c = 0; c < NCHK2; c++) {
        int buf = c & 1;
        uint32_t base = smb + buf * (BUFE2 * 2);
        bool more = (c + 1) < NCHK2;
        if (more) {
            LOAD_CHUNK2((c + 1) * KC2, buf ^ 1);
            CP_WAIT1();
        } else {
            CP_WAIT0();
        }
        __syncthreads();

#pragma unroll
        for (int s = 0; s < 2; s++) {
            uint32_t afr[3][2][4];
            uint32_t bfr[3][2][4];
            {
                int arow = wm * 32 + (lane & 15);
                int acol = s * 16 + (lane >> 4) * 8;
#pragma unroll
                for (int p = 0; p < 3; p++)
#pragma unroll
                    for (int mf = 0; mf < 2; mf++)
                        ldsm4(afr[p][mf],
                              base + (uint32_t)(p * PLA + (arow + mf * 16) * ST2 + acol) * 2);
                int nrow = wn * 32 + (lane & 7) + ((lane >> 4) & 1) * 8;
                int kcol = s * 16 + ((lane >> 3) & 1) * 8;
#pragma unroll
                for (int p = 0; p < 3; p++)
#pragma unroll
                    for (int g = 0; g < 2; g++)
                        ldsm4(bfr[p][g],
                              base + (uint32_t)(3 * PLA + p * PLB + (nrow + g * 16) * ST2 + kcol) * 2);
            }
            // term-outer: t=0 hh -> shh; t=1..5 hm,mh,hl,mm,lh -> srest
            // (same per-accumulator (k16, term) order as round 9/10: bitwise identical)
            const int pa_t[6] = {0, 0, 1, 0, 1, 2};
            const int pb_t[6] = {0, 1, 0, 2, 1, 0};
#pragma unroll
            for (int t = 0; t < 6; t++) {
                int pa = pa_t[t], pb = pb_t[t];
                float (*dst)[4][4] = (t == 0) ? shh : srest;
#pragma unroll
                for (int mf = 0; mf < 2; mf++)
#pragma unroll
                    for (int nf = 0; nf < 4; nf++)
                        mma_bf16(dst[mf][nf], afr[pa][mf],
                                 bfr[pb][nf >> 1][(nf & 1) * 2],
                                 bfr[pb][nf >> 1][(nf & 1) * 2 + 1]);
            }
        }
        __syncthreads();
    }

    // epilogue: v = rest + hh (one rounding) + fused per-batch min
    float lmin = 3.402823466e+38f;
    float* outb = out + (size_t)b * NN * NN;
#pragma unroll
    for (int mf = 0; mf < 2; mf++)
#pragma unroll
        for (int nf = 0; nf < 4; nf++) {
            int r = row0 + wm * 32 + mf * 16 + (lane >> 2);
            int cc = col0 + wn * 32 + nf * 8 + (lane & 3) * 2;
            float v0x = __fadd_rn(srest[mf][nf][0], shh[mf][nf][0]);
            float v0y = __fadd_rn(srest[mf][nf][1], shh[mf][nf][1]);
            float v1x = __fadd_rn(srest[mf][nf][2], shh[mf][nf][2]);
            float v1y = __fadd_rn(srest[mf][nf][3], shh[mf][nf][3]);
            *(float2*)(outb + (size_t)r * NN + cc) = make_float2(v0x, v0y);
            *(float2*)(outb + (size_t)(r + 8) * NN + cc) = make_float2(v1x, v1y);
            lmin = fminf(lmin, fminf(fminf(v0x, v0y), fminf(v1x, v1y)));
        }
#pragma unroll
    for (int off = 16; off > 0; off >>= 1)
        lmin = fminf(lmin, __shfl_xor_sync(0xFFFFFFFFu, lmin, off));
    __syncthreads();
    if (lane == 0) atomicMin(&sMin, fmap(lmin));
    __syncthreads();
    if (tid == 0) atomicMin(&g_minbits[b], sMin);
}

// ---------------- selection / apply (unchanged) ----------------
#define RT 256
#define EPT 8
__global__ __launch_bounds__(RT) void k_sel(const float* __restrict__ out,
                                            const float* __restrict__ mask) {
    __shared__ unsigned int hist[256];
    __shared__ unsigned int warpsum[8];
    __shared__ unsigned int s_digit, s_r;
    __shared__ float s_part[8];

    int row = blockIdx.x;
    int b = row >> 11;
    int tid = threadIdx.x;
    int lane = tid & 31;
    int warp = tid >> 5;
    float minb = funmap(g_minbits[b]);
    float mk = mask[row];
    const float* rp = out + (size_t)row * NN;

    float v[EPT];
    unsigned int key[EPT];
    {
        float4 x0 = *(const float4*)(rp + tid * EPT);
        float4 x1 = *(const float4*)(rp + tid * EPT + 4);
        float xv[8] = {x0.x, x0.y, x0.z, x0.w, x1.x, x1.y, x1.z, x1.w};
#pragma unroll
        for (int q = 0; q < EPT; q++) {
            v[q] = (xv[q] - minb) * mk;
            key[q] = fmap(v[q]);
        }
    }

    unsigned int prefix = 0;
    unsigned int r = KTOP;
#pragma unroll
    for (int shift = 24; shift >= 0; shift -= 8) {
        hist[tid] = 0;
        __syncthreads();
        unsigned int pmask = (shift == 24) ? 0u : (0xFFFFFFFFu << (shift + 8));
#pragma unroll
        for (int q = 0; q < EPT; q++) {
            unsigned int k = key[q];
            bool match = ((k & pmask) == prefix);
            unsigned int d = match ? ((k >> shift) & 0xFFu) : 0xFFFFFFFFu;
            unsigned int peers = __match_any_sync(0xFFFFFFFFu, d);
            if (match && (lane == (__ffs(peers) - 1)))
                atomicAdd(&hist[d], __popc(peers));
        }
        __syncthreads();
        unsigned int h = hist[tid];
        unsigned int s = h;
#pragma unroll
        for (int off = 1; off < 32; off <<= 1) {
            unsigned int t = __shfl_down_sync(0xFFFFFFFFu, s, off);
            if (lane + off < 32) s += t;
        }
        if (lane == 0) warpsum[warp] = s;
        __syncthreads();
        unsigned int woff = 0;
#pragma unroll
        for (int w = 0; w < 8; w++)
            if (w > warp) woff += warpsum[w];
        unsigned int suffix = s + woff;
        if (suffix >= r && suffix - h < r) {
            s_digit = (unsigned int)tid;
            s_r = r - (suffix - h);
        }
        __syncthreads();
        prefix |= (s_digit << shift);
        r = s_r;
    }
    unsigned int T = prefix;
    unsigned int eq_needed = r;

    float lsum = 0.f;
#pragma unroll
    for (int q = 0; q < EPT; q++)
        if (key[q] > T) lsum += v[q];
#pragma unroll
    for (int off = 16; off > 0; off >>= 1) lsum += __shfl_xor_sync(0xFFFFFFFFu, lsum, off);
    if (lane == 0) s_part[warp] = lsum;
    __syncthreads();
    if (tid == 0) {
        float tot = 0.f;
#pragma unroll
        for (int w = 0; w < 8; w++) tot += s_part[w];
        tot += (float)eq_needed * funmap(T);
        float d = (tot > 0.f) ? (1.0f / sqrtf(tot)) : 0.0f;
        g_dinv[row] = d;
        g_T[row] = T;
        g_eq[row] = eq_needed;
    }
}

__global__ __launch_bounds__(RT) void k_apply(float* __restrict__ out,
                                              const float* __restrict__ mask) {
    __shared__ unsigned int s_w[8];

    int row = blockIdx.x;
    int b = row >> 11;
    int tid = threadIdx.x;
    int lane = tid & 31;
    int warp = tid >> 5;
    float minb = funmap(g_minbits[b]);
    float mk = mask[row];
    unsigned int T = g_T[row];
    unsigned int eq = g_eq[row];
    float di = g_dinv[row];
    float* rp = out + (size_t)row * NN;

    float v[EPT];
    unsigned int key[EPT];
    {
        float4 x0 = *(const float4*)(rp + tid * EPT);
        float4 x1 = *(const float4*)(rp + tid * EPT + 4);
        float xv[8] = {x0.x, x0.y, x0.z, x0.w, x1.x, x1.y, x1.z, x1.w};
#pragma unroll
        for (int q = 0; q < EPT; q++) {
            v[q] = (xv[q] - minb) * mk;
            key[q] = fmap(v[q]);
        }
    }

    unsigned int cnt = 0;
#pragma unroll
    for (int q = 0; q < EPT; q++) cnt += (key[q] == T) ? 1u : 0u;
    unsigned int incl = cnt;
#pragma unroll
    for (int off = 1; off < 32; off <<= 1) {
        unsigned int t = __shfl_up_sync(0xFFFFFFFFu, incl, off);
        if (lane >= off) incl += t;
    }
    if (lane == 31) s_w[warp] = incl;
    __syncthreads();
    unsigned int woff = 0;
#pragma unroll
    for (int w = 0; w < 8; w++)
        if (w < warp) woff += s_w[w];
    unsigned int rank = woff + incl - cnt;

    float dj[EPT];
    {
        float4 d0 = *(const float4*)(g_dinv + ((size_t)b << 11) + tid * EPT);
        float4 d1 = *(const float4*)(g_dinv + ((size_t)b << 11) + tid * EPT + 4);
        dj[0] = d0.x; dj[1] = d0.y; dj[2] = d0.z; dj[3] = d0.w;
        dj[4] = d1.x; dj[5] = d1.y; dj[6] = d1.z; dj[7] = d1.w;
    }

    float o[EPT];
#pragma unroll
    for (int q = 0; q < EPT; q++) {
        unsigned int k = key[q];
        bool keep = (k > T) || (k == T && rank < eq);
        if (k == T) rank++;
        o[q] = keep ? (di * v[q]) * dj[q] : 0.0f;
    }
    float4 y0 = make_float4(o[0], o[1], o[2], o[3]);
    float4 y1 = make_float4(o[4], o[5], o[6], o[7]);
    *(float4*)(rp + tid * EPT) = y0;
    *(float4*)(rp + tid * EPT + 4) = y1;
}

extern "C" void kernel_launch(void* const* d_in, const int* in_sizes, int n_in,
                              void* d_out, int out_size) {
    const float* ge = (const float*)d_in[0];
    const float* mask = (const float*)d_in[1];
    const float* hs = (const float*)d_in[2];
    const float* W1 = (const float*)d_in[3];
    const float* b1 = (const float*)d_in[4];
    const float* W2 = (const float*)d_in[5];
    const float* b2 = (const float*)d_in[6];
    float* out = (float*)d_out;

    cudaFuncSetAttribute(k_gemm2m, cudaFuncAttributeMaxDynamicSharedMemorySize, SMEMB2);

    k_init<<<1, 32>>>();
    k_hb<<<BB, 512>>>(hs, W1, W2);
    k_gemm1<<<dim3(4, (BB * NN) / BM), 256>>>(ge, mask, W1, b1, W2, b2);
    k_gemm2m<<<dim3(NN / 64, NN / 128, BB), 256, SMEMB2>>>(out);
    k_sel<<<BB * NN, RT>>>(out, mask);
    k_apply<<<BB * NN, RT>>>(out, mask);
}